// round 2
// baseline (speedup 1.0000x reference)
#include <cuda_runtime.h>
#include <mma.h>
#include <math.h>

using namespace nvcuda;

#define D_MODEL 512
#define N_HEADS 8
#define HEAD_DIM 64
#define D_FF 2048
#define SEQ 4096
#define BATCH 2
#define ROWS (BATCH*SEQ)      /* 8192 */
#define BH (BATCH*N_HEADS)    /* 16 */

// ---------------- scratch (no allocations allowed) ----------------
__device__ float  g_xln [ROWS*D_MODEL];
__device__ float  g_qkv [ROWS*3*D_MODEL];
__device__ float  g_Q   [BH*SEQ*HEAD_DIM];
__device__ float  g_Kv  [BH*SEQ*HEAD_DIM];
__device__ float  g_Vv  [BH*SEQ*HEAD_DIM];
__device__ float  g_ctx [ROWS*D_MODEL];
__device__ float  g_src2[ROWS*D_MODEL];
__device__ float  g_h   [ROWS*D_FF];
__device__ float2 g_rope[SEQ*32];

// ---------------- LayerNorm: one block per row of 512 ----------------
__global__ void __launch_bounds__(128) ln_kernel(const float* __restrict__ x,
                                                 const float* __restrict__ w,
                                                 const float* __restrict__ b,
                                                 float* __restrict__ y)
{
    int row = blockIdx.x;
    int t = threadIdx.x;
    const float4* xr = reinterpret_cast<const float4*>(x) + (size_t)row * 128;
    float4 v = xr[t];
    float s  = v.x + v.y + v.z + v.w;
    float ss = v.x*v.x + v.y*v.y + v.z*v.z + v.w*v.w;
    #pragma unroll
    for (int off = 16; off >= 1; off >>= 1) {
        s  += __shfl_xor_sync(0xffffffffu, s,  off);
        ss += __shfl_xor_sync(0xffffffffu, ss, off);
    }
    __shared__ float rs[4], rss[4];
    int wid = t >> 5;
    if ((t & 31) == 0) { rs[wid] = s; rss[wid] = ss; }
    __syncthreads();
    s  = rs[0] + rs[1] + rs[2] + rs[3];
    ss = rss[0] + rss[1] + rss[2] + rss[3];
    float mu  = s * (1.0f / 512.0f);
    float var = ss * (1.0f / 512.0f) - mu * mu;
    float r   = rsqrtf(var + 1e-5f);
    float4 w4 = reinterpret_cast<const float4*>(w)[t];
    float4 b4 = reinterpret_cast<const float4*>(b)[t];
    float4 o4;
    o4.x = (v.x - mu) * r * w4.x + b4.x;
    o4.y = (v.y - mu) * r * w4.y + b4.y;
    o4.z = (v.z - mu) * r * w4.z + b4.z;
    o4.w = (v.w - mu) * r * w4.w + b4.w;
    reinterpret_cast<float4*>(y)[(size_t)row * 128 + t] = o4;
}

// ---------------- TF32 wmma NT GEMM: C[M,N] = A[M,K] * W[N,K]^T (+bias, relu, resid) -----
// 128x128 block tile, BK=32, 8 warps in 4x2, warp tile 32x64 (2x4 16x16 frags)
#define GLDA 36
template<bool RELU, bool RESID>
__global__ void __launch_bounds__(256) gemm_tf32(const float* __restrict__ A,
                                                 const float* __restrict__ W,
                                                 const float* __restrict__ bias,
                                                 const float* __restrict__ resid,
                                                 float* __restrict__ C,
                                                 int M, int N, int K)
{
    __shared__ float As[128 * GLDA];
    __shared__ float Ws[128 * GLDA];
    int tid = threadIdx.x;
    int wid = tid >> 5, lane = tid & 31;
    int wr = wid >> 1, wc = wid & 1;
    int bm = blockIdx.y * 128, bn = blockIdx.x * 128;

    wmma::fragment<wmma::accumulator, 16, 16, 8, float> acc[2][4];
    #pragma unroll
    for (int i = 0; i < 2; i++)
        #pragma unroll
        for (int j = 0; j < 4; j++) wmma::fill_fragment(acc[i][j], 0.0f);

    for (int k0 = 0; k0 < K; k0 += 32) {
        #pragma unroll
        for (int it = 0; it < 4; ++it) {
            int lin = tid + it * 256;         // float4 index 0..1023
            int row = lin >> 3;
            int c4  = (lin & 7) * 4;
            float4 va = *reinterpret_cast<const float4*>(&A[(size_t)(bm + row) * K + k0 + c4]);
            *reinterpret_cast<float4*>(&As[row * GLDA + c4]) = va;
            float4 vw = *reinterpret_cast<const float4*>(&W[(size_t)(bn + row) * K + k0 + c4]);
            *reinterpret_cast<float4*>(&Ws[row * GLDA + c4]) = vw;
        }
        __syncthreads();
        #pragma unroll
        for (int ks = 0; ks < 4; ks++) {
            int k8 = ks * 8;
            wmma::fragment<wmma::matrix_a, 16, 16, 8, wmma::precision::tf32, wmma::row_major> af[2];
            #pragma unroll
            for (int i = 0; i < 2; i++) {
                wmma::load_matrix_sync(af[i], &As[(wr * 32 + i * 16) * GLDA + k8], GLDA);
                #pragma unroll
                for (int t = 0; t < af[i].num_elements; t++)
                    af[i].x[t] = wmma::__float_to_tf32(af[i].x[t]);
            }
            wmma::fragment<wmma::matrix_b, 16, 16, 8, wmma::precision::tf32, wmma::col_major> bf[4];
            #pragma unroll
            for (int j = 0; j < 4; j++) {
                wmma::load_matrix_sync(bf[j], &Ws[(wc * 64 + j * 16) * GLDA + k8], GLDA);
                #pragma unroll
                for (int t = 0; t < bf[j].num_elements; t++)
                    bf[j].x[t] = wmma::__float_to_tf32(bf[j].x[t]);
            }
            #pragma unroll
            for (int i = 0; i < 2; i++)
                #pragma unroll
                for (int j = 0; j < 4; j++)
                    wmma::mma_sync(acc[i][j], af[i], bf[j], acc[i][j]);
        }
        __syncthreads();
    }

    // epilogue via per-warp smem patch (reuse As)
    float* cbuf = As + wid * 16 * 20;
    #pragma unroll
    for (int i = 0; i < 2; i++) {
        #pragma unroll
        for (int j = 0; j < 4; j++) {
            wmma::store_matrix_sync(cbuf, acc[i][j], 20, wmma::mem_row_major);
            __syncwarp();
            #pragma unroll
            for (int u = 0; u < 2; u++) {
                int e = lane + u * 32;        // 0..63 float4 of 16x16
                int row = e >> 2, c4 = (e & 3) * 4;
                float4 o = *reinterpret_cast<float4*>(&cbuf[row * 20 + c4]);
                int gr = bm + wr * 32 + i * 16 + row;
                int gc = bn + wc * 64 + j * 16 + c4;
                float4 bb = *reinterpret_cast<const float4*>(&bias[gc]);
                o.x += bb.x; o.y += bb.y; o.z += bb.z; o.w += bb.w;
                if (RELU) {
                    o.x = fmaxf(o.x, 0.0f); o.y = fmaxf(o.y, 0.0f);
                    o.z = fmaxf(o.z, 0.0f); o.w = fmaxf(o.w, 0.0f);
                }
                if (RESID) {
                    float4 rv = *reinterpret_cast<const float4*>(&resid[(size_t)gr * N + gc]);
                    o.x += rv.x; o.y += rv.y; o.z += rv.z; o.w += rv.w;
                }
                *reinterpret_cast<float4*>(&C[(size_t)gr * N + gc]) = o;
            }
            __syncwarp();
        }
    }
}

// ---------------- RoPE cos/sin table: [SEQ][32] ----------------
__global__ void __launch_bounds__(256) rope_tab_kernel(float2* __restrict__ tab)
{
    int idx = blockIdx.x * 256 + threadIdx.x;
    int s = idx >> 5, i = idx & 31;
    double freq = 1.0 / pow(10000.0, (double)i / 32.0);
    float ang = (float)((double)s * freq);
    tab[idx] = make_float2(cosf(ang), sinf(ang));
}

// ---------------- split qkv -> Q (rope, pre-scaled), K (rope), V ; layout [B,H,S,D] -----
__global__ void __launch_bounds__(256) rope_split_kernel(const float* __restrict__ qkv,
                                                         const float2* __restrict__ tab,
                                                         float* __restrict__ Q,
                                                         float* __restrict__ K,
                                                         float* __restrict__ V)
{
    int idx = blockIdx.x * 256 + threadIdx.x;
    int d2 = idx & 31;
    int hh = (idx >> 5) & 7;
    int bs = idx >> 8;
    int s  = bs & (SEQ - 1);
    int b  = bs >> 12;
    const float* base = qkv + (size_t)bs * 1536 + hh * 64 + d2 * 2;
    float2 q = *reinterpret_cast<const float2*>(base);
    float2 k = *reinterpret_cast<const float2*>(base + 512);
    float2 v = *reinterpret_cast<const float2*>(base + 1024);
    float2 cs = tab[s * 32 + d2];
    size_t o = ((((size_t)b * 8 + hh) * SEQ) + s) * 64 + d2 * 2;
    const float sc = 0.125f;
    *reinterpret_cast<float2*>(&Q[o]) =
        make_float2((q.x * cs.x - q.y * cs.y) * sc, (q.x * cs.y + q.y * cs.x) * sc);
    *reinterpret_cast<float2*>(&K[o]) =
        make_float2(k.x * cs.x - k.y * cs.y, k.x * cs.y + k.y * cs.x);
    *reinterpret_cast<float2*>(&V[o]) = v;
}

// ---------------- causal flash attention with TF32 wmma, 64x64 tiles ----------------
#define FLD 68
// smem float offsets
#define SQ_OFF 0
#define SK_OFF (64*FLD)
#define SV_OFF (2*64*FLD)
#define SP_OFF (3*64*FLD)
#define SO_OFF (4*64*FLD)
#define SM_OFF (5*64*FLD)
#define SL_OFF (SM_OFF+64)
#define SAL_OFF (SM_OFF+128)
#define FLASH_SMEM ((SM_OFF+192)*4)

__global__ void __launch_bounds__(256) flash_tf32(const float* __restrict__ Qg,
                                                  const float* __restrict__ Kg,
                                                  const float* __restrict__ Vg,
                                                  float* __restrict__ ctx)
{
    extern __shared__ float sm[];
    float* Qs = sm + SQ_OFF;
    float* Ks = sm + SK_OFF;
    float* Vs = sm + SV_OFF;
    float* Ps = sm + SP_OFF;
    float* Os = sm + SO_OFF;
    float* m_s = sm + SM_OFF;
    float* l_s = sm + SL_OFF;
    float* al_s = sm + SAL_OFF;

    int qt = blockIdx.x;
    int bh = blockIdx.y;
    int b = bh >> 3, hh = bh & 7;
    const float* Qb = Qg + ((size_t)bh * SEQ + qt * 64) * 64;
    const float* Kb = Kg + (size_t)bh * SEQ * 64;
    const float* Vb = Vg + (size_t)bh * SEQ * 64;
    int tid = threadIdx.x;
    int wid = tid >> 5;
    int wr = wid >> 1, wc = wid & 1;   // warp computes rows wr*16..+16, cols wc*32..+32

    // load Q tile [q][d] row-major
    #pragma unroll
    for (int it = 0; it < 4; ++it) {
        int idx = tid + it * 256;
        int r = idx >> 4, c = (idx & 15) * 4;
        *reinterpret_cast<float4*>(&Qs[r * FLD + c]) =
            *reinterpret_cast<const float4*>(&Qb[r * 64 + c]);
    }
    // init O, stats
    for (int i = tid; i < 64 * FLD; i += 256) Os[i] = 0.0f;
    if (tid < 64) { m_s[tid] = -1e30f; l_s[tid] = 0.0f; }

    int row = tid >> 2;         // softmax row ownership
    int seg = tid & 3;

    for (int kt = 0; kt <= qt; ++kt) {
        __syncthreads();
        #pragma unroll
        for (int it = 0; it < 4; ++it) {
            int idx = tid + it * 256;
            int r = idx >> 4, c = (idx & 15) * 4;
            *reinterpret_cast<float4*>(&Ks[r * FLD + c]) =
                *reinterpret_cast<const float4*>(&Kb[(kt * 64 + r) * 64 + c]);
            *reinterpret_cast<float4*>(&Vs[r * FLD + c]) =
                *reinterpret_cast<const float4*>(&Vb[(kt * 64 + r) * 64 + c]);
        }
        __syncthreads();

        // ---- S = Q K^T (TF32 mma) ----
        {
            wmma::fragment<wmma::accumulator, 16, 16, 8, float> sacc[2];
            wmma::fill_fragment(sacc[0], 0.0f);
            wmma::fill_fragment(sacc[1], 0.0f);
            #pragma unroll
            for (int ks = 0; ks < 8; ks++) {
                int k8 = ks * 8;
                wmma::fragment<wmma::matrix_a, 16, 16, 8, wmma::precision::tf32, wmma::row_major> af;
                wmma::load_matrix_sync(af, &Qs[(wr * 16) * FLD + k8], FLD);
                #pragma unroll
                for (int t = 0; t < af.num_elements; t++)
                    af.x[t] = wmma::__float_to_tf32(af.x[t]);
                #pragma unroll
                for (int j = 0; j < 2; j++) {
                    wmma::fragment<wmma::matrix_b, 16, 16, 8, wmma::precision::tf32, wmma::col_major> bf;
                    wmma::load_matrix_sync(bf, &Ks[(wc * 32 + j * 16) * FLD + k8], FLD);
                    #pragma unroll
                    for (int t = 0; t < bf.num_elements; t++)
                        bf.x[t] = wmma::__float_to_tf32(bf.x[t]);
                    wmma::mma_sync(sacc[j], af, bf, sacc[j]);
                }
            }
            #pragma unroll
            for (int j = 0; j < 2; j++)
                wmma::store_matrix_sync(&Ps[(wr * 16) * FLD + wc * 32 + j * 16], sacc[j],
                                        FLD, wmma::mem_row_major);
        }
        __syncthreads();

        // ---- online softmax on Ps (4 threads per row, 16 cols each) ----
        {
            float sv[16];
            bool diag = (kt == qt);
            #pragma unroll
            for (int q4 = 0; q4 < 4; q4++) {
                float4 v = *reinterpret_cast<float4*>(&Ps[row * FLD + seg * 16 + q4 * 4]);
                sv[q4 * 4 + 0] = v.x; sv[q4 * 4 + 1] = v.y;
                sv[q4 * 4 + 2] = v.z; sv[q4 * 4 + 3] = v.w;
            }
            if (diag) {
                #pragma unroll
                for (int c = 0; c < 16; c++)
                    if (seg * 16 + c > row) sv[c] = -1e30f;
            }
            float mx = -1e30f;
            #pragma unroll
            for (int c = 0; c < 16; c++) mx = fmaxf(mx, sv[c]);
            mx = fmaxf(mx, __shfl_xor_sync(0xffffffffu, mx, 1));
            mx = fmaxf(mx, __shfl_xor_sync(0xffffffffu, mx, 2));
            float mo = m_s[row];
            float mn = fmaxf(mo, mx);
            float al = __expf(mo - mn);
            float sum = 0.0f;
            #pragma unroll
            for (int c = 0; c < 16; c++) { sv[c] = __expf(sv[c] - mn); sum += sv[c]; }
            sum += __shfl_xor_sync(0xffffffffu, sum, 1);
            sum += __shfl_xor_sync(0xffffffffu, sum, 2);
            if (seg == 0) {
                m_s[row] = mn;
                l_s[row] = l_s[row] * al + sum;
                al_s[row] = al;
            }
            #pragma unroll
            for (int q4 = 0; q4 < 4; q4++)
                *reinterpret_cast<float4*>(&Ps[row * FLD + seg * 16 + q4 * 4]) =
                    make_float4(sv[q4 * 4 + 0], sv[q4 * 4 + 1], sv[q4 * 4 + 2], sv[q4 * 4 + 3]);
        }
        __syncthreads();

        // ---- delta = P V (TF32 mma) ----
        {
            wmma::fragment<wmma::accumulator, 16, 16, 8, float> oacc[2];
            wmma::fill_fragment(oacc[0], 0.0f);
            wmma::fill_fragment(oacc[1], 0.0f);
            #pragma unroll
            for (int ks = 0; ks < 8; ks++) {
                int k8 = ks * 8;
                wmma::fragment<wmma::matrix_a, 16, 16, 8, wmma::precision::tf32, wmma::row_major> af;
                wmma::load_matrix_sync(af, &Ps[(wr * 16) * FLD + k8], FLD);
                #pragma unroll
                for (int t = 0; t < af.num_elements; t++)
                    af.x[t] = wmma::__float_to_tf32(af.x[t]);
                #pragma unroll
                for (int j = 0; j < 2; j++) {
                    wmma::fragment<wmma::matrix_b, 16, 16, 8, wmma::precision::tf32, wmma::row_major> bf;
                    wmma::load_matrix_sync(bf, &Vs[k8 * FLD + wc * 32 + j * 16], FLD);
                    #pragma unroll
                    for (int t = 0; t < bf.num_elements; t++)
                        bf.x[t] = wmma::__float_to_tf32(bf.x[t]);
                    wmma::mma_sync(oacc[j], af, bf, oacc[j]);
                }
            }
            __syncthreads();   // everyone done reading P
            #pragma unroll
            for (int j = 0; j < 2; j++)
                wmma::store_matrix_sync(&Ps[(wr * 16) * FLD + wc * 32 + j * 16], oacc[j],
                                        FLD, wmma::mem_row_major);
        }
        __syncthreads();

        // ---- O = O*al + delta ----
        {
            float al = al_s[row];
            #pragma unroll
            for (int q4 = 0; q4 < 4; q4++) {
                int c = seg * 16 + q4 * 4;
                float4 ov = *reinterpret_cast<float4*>(&Os[row * FLD + c]);
                float4 dv = *reinterpret_cast<float4*>(&Ps[row * FLD + c]);
                ov.x = ov.x * al + dv.x; ov.y = ov.y * al + dv.y;
                ov.z = ov.z * al + dv.z; ov.w = ov.w * al + dv.w;
                *reinterpret_cast<float4*>(&Os[row * FLD + c]) = ov;
            }
        }
    }
    __syncthreads();

    // finalize: ctx[b][s][h*64+d] = O / l
    {
        float inv = 1.0f / l_s[row];
        int srow = qt * 64 + row;
        size_t off = ((size_t)b * SEQ + srow) * 512 + hh * 64 + seg * 16;
        #pragma unroll
        for (int q4 = 0; q4 < 4; q4++) {
            float4 ov = *reinterpret_cast<float4*>(&Os[row * FLD + seg * 16 + q4 * 4]);
            *reinterpret_cast<float4*>(&ctx[off + q4 * 4]) =
                make_float4(ov.x * inv, ov.y * inv, ov.z * inv, ov.w * inv);
        }
    }
}

// ---------------- launch ----------------
extern "C" void kernel_launch(void* const* d_in, const int* in_sizes, int n_in,
                              void* d_out, int out_size)
{
    const float* src      = (const float*)d_in[0];
    const float* ln_w     = (const float*)d_in[1];
    const float* ln_b     = (const float*)d_in[2];
    const float* wqkv_w   = (const float*)d_in[3];
    const float* wqkv_b   = (const float*)d_in[4];
    const float* out_w    = (const float*)d_in[5];
    const float* out_b    = (const float*)d_in[6];
    const float* ffn_ln_w = (const float*)d_in[7];
    const float* ffn_ln_b = (const float*)d_in[8];
    const float* ff1_w    = (const float*)d_in[9];
    const float* ff1_b    = (const float*)d_in[10];
    const float* ff2_w    = (const float*)d_in[11];
    const float* ff2_b    = (const float*)d_in[12];
    float* out = (float*)d_out;

    float *xln, *qkv, *Q, *K, *V, *ctx, *src2, *hbuf;
    float2* tab;
    cudaGetSymbolAddress((void**)&xln,  g_xln);
    cudaGetSymbolAddress((void**)&qkv,  g_qkv);
    cudaGetSymbolAddress((void**)&Q,    g_Q);
    cudaGetSymbolAddress((void**)&K,    g_Kv);
    cudaGetSymbolAddress((void**)&V,    g_Vv);
    cudaGetSymbolAddress((void**)&ctx,  g_ctx);
    cudaGetSymbolAddress((void**)&src2, g_src2);
    cudaGetSymbolAddress((void**)&hbuf, g_h);
    cudaGetSymbolAddress((void**)&tab,  g_rope);

    cudaFuncSetAttribute(flash_tf32, cudaFuncAttributeMaxDynamicSharedMemorySize, FLASH_SMEM);

    // 1. LN(src)
    ln_kernel<<<ROWS, 128>>>(src, ln_w, ln_b, xln);
    // 2. QKV projection
    gemm_tf32<false, false><<<dim3(12, 64), 256>>>(xln, wqkv_w, wqkv_b, nullptr, qkv,
                                                   ROWS, 3 * D_MODEL, D_MODEL);
    // 3. RoPE table + split/transpose
    rope_tab_kernel<<<(SEQ * 32) / 256, 256>>>(tab);
    rope_split_kernel<<<(ROWS * 8 * 32) / 256, 256>>>(qkv, tab, Q, K, V);
    // 4. causal flash attention
    flash_tf32<<<dim3(SEQ / 64, BH), 256, FLASH_SMEM>>>(Q, K, V, ctx);
    // 5. out projection + residual
    gemm_tf32<false, true><<<dim3(4, 64), 256>>>(ctx, out_w, out_b, src, src2,
                                                 ROWS, D_MODEL, D_MODEL);
    // 6. LN2
    ln_kernel<<<ROWS, 128>>>(src2, ffn_ln_w, ffn_ln_b, xln);
    // 7. FF1 + relu
    gemm_tf32<true, false><<<dim3(16, 64), 256>>>(xln, ff1_w, ff1_b, nullptr, hbuf,
                                                  ROWS, D_FF, D_MODEL);
    // 8. FF2 + residual -> out
    gemm_tf32<false, true><<<dim3(4, 64), 256>>>(hbuf, ff2_w, ff2_b, src2, out,
                                                 ROWS, D_MODEL, D_FF);
}

// round 3
// speedup vs baseline: 3.0362x; 3.0362x over previous
#include <cuda_runtime.h>
#include <cuda_fp16.h>
#include <mma.h>
#include <math.h>

using namespace nvcuda;

#define D_MODEL 512
#define N_HEADS 8
#define HEAD_DIM 64
#define D_FF 2048
#define SEQ 4096
#define BATCH 2
#define ROWS (BATCH*SEQ)      /* 8192 */
#define BH (BATCH*N_HEADS)    /* 16 */

// ---------------- scratch (no allocations allowed) ----------------
__device__ __half  g_xln_h [ROWS*D_MODEL];
__device__ float   g_qkv   [ROWS*3*D_MODEL];
__device__ __half  g_Qh    [BH*SEQ*HEAD_DIM];
__device__ __half  g_Kh    [BH*SEQ*HEAD_DIM];
__device__ __half  g_Vh    [BH*SEQ*HEAD_DIM];
__device__ __half  g_ctx_h [ROWS*D_MODEL];
__device__ float   g_src2  [ROWS*D_MODEL];
__device__ __half  g_hid_h [ROWS*D_FF];
__device__ float2  g_rope  [SEQ*32];
// half weights
__device__ __half  g_wqkv_h[3*D_MODEL*D_MODEL];
__device__ __half  g_outw_h[D_MODEL*D_MODEL];
__device__ __half  g_ff1_h [D_FF*D_MODEL];
__device__ __half  g_ff2_h [D_MODEL*D_FF];

// ---------------- fp32 -> fp16 conversion ----------------
__global__ void __launch_bounds__(256) f2h_kernel(const float* __restrict__ in,
                                                  __half* __restrict__ out, int n4)
{
    int i = blockIdx.x * 256 + threadIdx.x;
    if (i < n4) {
        float4 v = reinterpret_cast<const float4*>(in)[i];
        __half2 h0 = __floats2half2_rn(v.x, v.y);
        __half2 h1 = __floats2half2_rn(v.z, v.w);
        reinterpret_cast<__half2*>(out)[i * 2 + 0] = h0;
        reinterpret_cast<__half2*>(out)[i * 2 + 1] = h1;
    }
}

// ---------------- LayerNorm: one block per row of 512, half output ----------------
__global__ void __launch_bounds__(128) ln_kernel(const float* __restrict__ x,
                                                 const float* __restrict__ w,
                                                 const float* __restrict__ b,
                                                 __half* __restrict__ y)
{
    int row = blockIdx.x;
    int t = threadIdx.x;
    const float4* xr = reinterpret_cast<const float4*>(x) + (size_t)row * 128;
    float4 v = xr[t];
    float s  = v.x + v.y + v.z + v.w;
    float ss = v.x*v.x + v.y*v.y + v.z*v.z + v.w*v.w;
    #pragma unroll
    for (int off = 16; off >= 1; off >>= 1) {
        s  += __shfl_xor_sync(0xffffffffu, s,  off);
        ss += __shfl_xor_sync(0xffffffffu, ss, off);
    }
    __shared__ float rs[4], rss[4];
    int wid = t >> 5;
    if ((t & 31) == 0) { rs[wid] = s; rss[wid] = ss; }
    __syncthreads();
    s  = rs[0] + rs[1] + rs[2] + rs[3];
    ss = rss[0] + rss[1] + rss[2] + rss[3];
    float mu  = s * (1.0f / 512.0f);
    float var = ss * (1.0f / 512.0f) - mu * mu;
    float r   = rsqrtf(var + 1e-5f);
    float4 w4 = reinterpret_cast<const float4*>(w)[t];
    float4 b4 = reinterpret_cast<const float4*>(b)[t];
    float ox = (v.x - mu) * r * w4.x + b4.x;
    float oy = (v.y - mu) * r * w4.y + b4.y;
    float oz = (v.z - mu) * r * w4.z + b4.z;
    float ow = (v.w - mu) * r * w4.w + b4.w;
    __half2* yr = reinterpret_cast<__half2*>(y) + (size_t)row * 256;
    yr[t * 2 + 0] = __floats2half2_rn(ox, oy);
    yr[t * 2 + 1] = __floats2half2_rn(oz, ow);
}

// ---------------- fp16 wmma NT GEMM: C[M,N] = A[M,K] * W[N,K]^T (+bias, relu, resid) ---
// 128x128 tile, BK=32, 8 warps 4x2, warp 32x64 (2x4 16x16x16 frags)
#define HLDA 40
template<bool RELU, bool RESID, bool OUTH>
__global__ void __launch_bounds__(256) gemm_h(const __half* __restrict__ A,
                                              const __half* __restrict__ W,
                                              const float* __restrict__ bias,
                                              const float* __restrict__ resid,
                                              float* __restrict__ C,
                                              __half* __restrict__ Ch,
                                              int M, int N, int K)
{
    __shared__ __half As[128 * HLDA];
    __shared__ __half Ws[128 * HLDA];
    int tid = threadIdx.x;
    int wid = tid >> 5, lane = tid & 31;
    int wr = wid >> 1, wc = wid & 1;
    int bm = blockIdx.y * 128, bn = blockIdx.x * 128;

    wmma::fragment<wmma::accumulator, 16, 16, 16, float> acc[2][4];
    #pragma unroll
    for (int i = 0; i < 2; i++)
        #pragma unroll
        for (int j = 0; j < 4; j++) wmma::fill_fragment(acc[i][j], 0.0f);

    for (int k0 = 0; k0 < K; k0 += 32) {
        #pragma unroll
        for (int it = 0; it < 2; ++it) {
            int lin = tid + it * 256;         // 8-half chunk index, 0..511
            int row = lin >> 2;
            int ch  = (lin & 3) * 8;
            *reinterpret_cast<int4*>(&As[row * HLDA + ch]) =
                *reinterpret_cast<const int4*>(&A[(size_t)(bm + row) * K + k0 + ch]);
            *reinterpret_cast<int4*>(&Ws[row * HLDA + ch]) =
                *reinterpret_cast<const int4*>(&W[(size_t)(bn + row) * K + k0 + ch]);
        }
        __syncthreads();
        #pragma unroll
        for (int ks = 0; ks < 2; ks++) {
            int k16 = ks * 16;
            wmma::fragment<wmma::matrix_a, 16, 16, 16, __half, wmma::row_major> af[2];
            #pragma unroll
            for (int i = 0; i < 2; i++)
                wmma::load_matrix_sync(af[i], &As[(wr * 32 + i * 16) * HLDA + k16], HLDA);
            wmma::fragment<wmma::matrix_b, 16, 16, 16, __half, wmma::col_major> bf[4];
            #pragma unroll
            for (int j = 0; j < 4; j++)
                wmma::load_matrix_sync(bf[j], &Ws[(wc * 64 + j * 16) * HLDA + k16], HLDA);
            #pragma unroll
            for (int i = 0; i < 2; i++)
                #pragma unroll
                for (int j = 0; j < 4; j++)
                    wmma::mma_sync(acc[i][j], af[i], bf[j], acc[i][j]);
        }
        __syncthreads();
    }

    // epilogue via per-warp smem patch (reuse As+Ws as float scratch)
    float* cbuf = reinterpret_cast<float*>(As) + wid * 16 * 20;
    #pragma unroll
    for (int i = 0; i < 2; i++) {
        #pragma unroll
        for (int j = 0; j < 4; j++) {
            wmma::store_matrix_sync(cbuf, acc[i][j], 20, wmma::mem_row_major);
            __syncwarp();
            #pragma unroll
            for (int u = 0; u < 2; u++) {
                int e = lane + u * 32;
                int row = e >> 2, c4 = (e & 3) * 4;
                float4 o = *reinterpret_cast<float4*>(&cbuf[row * 20 + c4]);
                int gr = bm + wr * 32 + i * 16 + row;
                int gc = bn + wc * 64 + j * 16 + c4;
                float4 bb = *reinterpret_cast<const float4*>(&bias[gc]);
                o.x += bb.x; o.y += bb.y; o.z += bb.z; o.w += bb.w;
                if (RELU) {
                    o.x = fmaxf(o.x, 0.0f); o.y = fmaxf(o.y, 0.0f);
                    o.z = fmaxf(o.z, 0.0f); o.w = fmaxf(o.w, 0.0f);
                }
                if (RESID) {
                    float4 rv = *reinterpret_cast<const float4*>(&resid[(size_t)gr * N + gc]);
                    o.x += rv.x; o.y += rv.y; o.z += rv.z; o.w += rv.w;
                }
                if (OUTH) {
                    __half2 h0 = __floats2half2_rn(o.x, o.y);
                    __half2 h1 = __floats2half2_rn(o.z, o.w);
                    *reinterpret_cast<__half2*>(&Ch[(size_t)gr * N + gc])     = h0;
                    *reinterpret_cast<__half2*>(&Ch[(size_t)gr * N + gc + 2]) = h1;
                } else {
                    *reinterpret_cast<float4*>(&C[(size_t)gr * N + gc]) = o;
                }
            }
            __syncwarp();
        }
    }
}

// ---------------- RoPE cos/sin table: [SEQ][32] ----------------
__global__ void __launch_bounds__(256) rope_tab_kernel(float2* __restrict__ tab)
{
    int idx = blockIdx.x * 256 + threadIdx.x;
    int s = idx >> 5, i = idx & 31;
    double freq = 1.0 / pow(10000.0, (double)i / 32.0);
    float ang = (float)((double)s * freq);
    tab[idx] = make_float2(cosf(ang), sinf(ang));
}

// ---------------- split qkv -> Q (rope, pre-scaled), K (rope), V half [B,H,S,D] --------
__global__ void __launch_bounds__(256) rope_split_kernel(const float* __restrict__ qkv,
                                                         const float2* __restrict__ tab,
                                                         __half* __restrict__ Q,
                                                         __half* __restrict__ K,
                                                         __half* __restrict__ V)
{
    int idx = blockIdx.x * 256 + threadIdx.x;
    int d2 = idx & 31;
    int hh = (idx >> 5) & 7;
    int bs = idx >> 8;
    int s  = bs & (SEQ - 1);
    int b  = bs >> 12;
    const float* base = qkv + (size_t)bs * 1536 + hh * 64 + d2 * 2;
    float2 q = *reinterpret_cast<const float2*>(base);
    float2 k = *reinterpret_cast<const float2*>(base + 512);
    float2 v = *reinterpret_cast<const float2*>(base + 1024);
    float2 cs = tab[s * 32 + d2];
    size_t o = ((((size_t)b * 8 + hh) * SEQ) + s) * 64 + d2 * 2;
    const float sc = 0.125f;
    reinterpret_cast<__half2*>(Q)[o >> 1] =
        __floats2half2_rn((q.x * cs.x - q.y * cs.y) * sc, (q.x * cs.y + q.y * cs.x) * sc);
    reinterpret_cast<__half2*>(K)[o >> 1] =
        __floats2half2_rn(k.x * cs.x - k.y * cs.y, k.x * cs.y + k.y * cs.x);
    reinterpret_cast<__half2*>(V)[o >> 1] = __floats2half2_rn(v.x, v.y);
}

// ---------------- causal flash attention with fp16 wmma, 64x64 tiles ----------------
#define HLD 72
#define PLD 68
// byte offsets in dynamic smem
#define OQS 0
#define OKS 9216
#define OVS 18432
#define OPH 27648
#define OPS 36864
#define OOS 54272
#define OST 71680
#define FLASH_SMEM (OST + 768)

__global__ void __launch_bounds__(256) flash_h(const __half* __restrict__ Qg,
                                               const __half* __restrict__ Kg,
                                               const __half* __restrict__ Vg,
                                               __half* __restrict__ ctx)
{
    extern __shared__ char smraw[];
    __half* Qs = reinterpret_cast<__half*>(smraw + OQS);
    __half* Ks = reinterpret_cast<__half*>(smraw + OKS);
    __half* Vs = reinterpret_cast<__half*>(smraw + OVS);
    __half* Ph = reinterpret_cast<__half*>(smraw + OPH);
    float*  Ps = reinterpret_cast<float*>(smraw + OPS);
    float*  Os = reinterpret_cast<float*>(smraw + OOS);
    float*  m_s  = reinterpret_cast<float*>(smraw + OST);
    float*  l_s  = m_s + 64;
    float*  al_s = m_s + 128;

    int qt = blockIdx.x;
    int bh = blockIdx.y;
    int b = bh >> 3, hh = bh & 7;
    const __half* Qb = Qg + ((size_t)bh * SEQ + qt * 64) * 64;
    const __half* Kb = Kg + (size_t)bh * SEQ * 64;
    const __half* Vb = Vg + (size_t)bh * SEQ * 64;
    int tid = threadIdx.x;
    int wid = tid >> 5;
    int wr = wid >> 1, wc = wid & 1;

    // load Q tile [q][d] half
    #pragma unroll
    for (int it = 0; it < 2; ++it) {
        int idx = tid + it * 256;    // 8-half chunks: 64 rows * 8 chunks
        int r = idx >> 3, c = (idx & 7) * 8;
        *reinterpret_cast<int4*>(&Qs[r * HLD + c]) =
            *reinterpret_cast<const int4*>(&Qb[r * 64 + c]);
    }
    for (int i = tid; i < 64 * PLD; i += 256) Os[i] = 0.0f;
    if (tid < 64) { m_s[tid] = -1e30f; l_s[tid] = 0.0f; }

    int row = tid >> 2;
    int seg = tid & 3;

    for (int kt = 0; kt <= qt; ++kt) {
        __syncthreads();
        #pragma unroll
        for (int it = 0; it < 2; ++it) {
            int idx = tid + it * 256;
            int r = idx >> 3, c = (idx & 7) * 8;
            *reinterpret_cast<int4*>(&Ks[r * HLD + c]) =
                *reinterpret_cast<const int4*>(&Kb[(kt * 64 + r) * 64 + c]);
            *reinterpret_cast<int4*>(&Vs[r * HLD + c]) =
                *reinterpret_cast<const int4*>(&Vb[(kt * 64 + r) * 64 + c]);
        }
        __syncthreads();

        // ---- S = Q K^T ----
        {
            wmma::fragment<wmma::accumulator, 16, 16, 16, float> sacc[2];
            wmma::fill_fragment(sacc[0], 0.0f);
            wmma::fill_fragment(sacc[1], 0.0f);
            #pragma unroll
            for (int ks = 0; ks < 4; ks++) {
                int k16 = ks * 16;
                wmma::fragment<wmma::matrix_a, 16, 16, 16, __half, wmma::row_major> af;
                wmma::load_matrix_sync(af, &Qs[(wr * 16) * HLD + k16], HLD);
                #pragma unroll
                for (int j = 0; j < 2; j++) {
                    wmma::fragment<wmma::matrix_b, 16, 16, 16, __half, wmma::col_major> bf;
                    wmma::load_matrix_sync(bf, &Ks[(wc * 32 + j * 16) * HLD + k16], HLD);
                    wmma::mma_sync(sacc[j], af, bf, sacc[j]);
                }
            }
            #pragma unroll
            for (int j = 0; j < 2; j++)
                wmma::store_matrix_sync(&Ps[(wr * 16) * PLD + wc * 32 + j * 16], sacc[j],
                                        PLD, wmma::mem_row_major);
        }
        __syncthreads();

        // ---- online softmax: read Ps (fp32), write Ph (half) ----
        {
            float sv[16];
            bool diag = (kt == qt);
            #pragma unroll
            for (int q4 = 0; q4 < 4; q4++) {
                float4 v = *reinterpret_cast<float4*>(&Ps[row * PLD + seg * 16 + q4 * 4]);
                sv[q4 * 4 + 0] = v.x; sv[q4 * 4 + 1] = v.y;
                sv[q4 * 4 + 2] = v.z; sv[q4 * 4 + 3] = v.w;
            }
            if (diag) {
                #pragma unroll
                for (int c = 0; c < 16; c++)
                    if (seg * 16 + c > row) sv[c] = -1e30f;
            }
            float mx = -1e30f;
            #pragma unroll
            for (int c = 0; c < 16; c++) mx = fmaxf(mx, sv[c]);
            mx = fmaxf(mx, __shfl_xor_sync(0xffffffffu, mx, 1));
            mx = fmaxf(mx, __shfl_xor_sync(0xffffffffu, mx, 2));
            float mo = m_s[row];
            float mn = fmaxf(mo, mx);
            float al = __expf(mo - mn);
            float sum = 0.0f;
            #pragma unroll
            for (int c = 0; c < 16; c++) { sv[c] = __expf(sv[c] - mn); sum += sv[c]; }
            sum += __shfl_xor_sync(0xffffffffu, sum, 1);
            sum += __shfl_xor_sync(0xffffffffu, sum, 2);
            if (seg == 0) {
                m_s[row] = mn;
                l_s[row] = l_s[row] * al + sum;
                al_s[row] = al;
            }
            #pragma unroll
            for (int c2 = 0; c2 < 8; c2++)
                *reinterpret_cast<__half2*>(&Ph[row * HLD + seg * 16 + c2 * 2]) =
                    __floats2half2_rn(sv[c2 * 2], sv[c2 * 2 + 1]);
        }
        __syncthreads();

        // ---- delta = P V ----
        {
            wmma::fragment<wmma::accumulator, 16, 16, 16, float> oacc[2];
            wmma::fill_fragment(oacc[0], 0.0f);
            wmma::fill_fragment(oacc[1], 0.0f);
            #pragma unroll
            for (int ks = 0; ks < 4; ks++) {
                int k16 = ks * 16;
                wmma::fragment<wmma::matrix_a, 16, 16, 16, __half, wmma::row_major> af;
                wmma::load_matrix_sync(af, &Ph[(wr * 16) * HLD + k16], HLD);
                #pragma unroll
                for (int j = 0; j < 2; j++) {
                    wmma::fragment<wmma::matrix_b, 16, 16, 16, __half, wmma::row_major> bf;
                    wmma::load_matrix_sync(bf, &Vs[k16 * HLD + wc * 32 + j * 16], HLD);
                    wmma::mma_sync(oacc[j], af, bf, oacc[j]);
                }
            }
            #pragma unroll
            for (int j = 0; j < 2; j++)
                wmma::store_matrix_sync(&Ps[(wr * 16) * PLD + wc * 32 + j * 16], oacc[j],
                                        PLD, wmma::mem_row_major);
        }
        __syncthreads();

        // ---- O = O*al + delta ----
        {
            float al = al_s[row];
            #pragma unroll
            for (int q4 = 0; q4 < 4; q4++) {
                int c = seg * 16 + q4 * 4;
                float4 ov = *reinterpret_cast<float4*>(&Os[row * PLD + c]);
                float4 dv = *reinterpret_cast<float4*>(&Ps[row * PLD + c]);
                ov.x = ov.x * al + dv.x; ov.y = ov.y * al + dv.y;
                ov.z = ov.z * al + dv.z; ov.w = ov.w * al + dv.w;
                *reinterpret_cast<float4*>(&Os[row * PLD + c]) = ov;
            }
        }
    }
    __syncthreads();

    // finalize: ctx_h[b][s][h*64+d] = O / l (half)
    {
        float inv = 1.0f / l_s[row];
        int srow = qt * 64 + row;
        size_t off = ((size_t)b * SEQ + srow) * 512 + hh * 64 + seg * 16;
        #pragma unroll
        for (int q4 = 0; q4 < 4; q4++) {
            float4 ov = *reinterpret_cast<float4*>(&Os[row * PLD + seg * 16 + q4 * 4]);
            *reinterpret_cast<__half2*>(&ctx[off + q4 * 4])     = __floats2half2_rn(ov.x * inv, ov.y * inv);
            *reinterpret_cast<__half2*>(&ctx[off + q4 * 4 + 2]) = __floats2half2_rn(ov.z * inv, ov.w * inv);
        }
    }
}

// ---------------- launch ----------------
extern "C" void kernel_launch(void* const* d_in, const int* in_sizes, int n_in,
                              void* d_out, int out_size)
{
    const float* src      = (const float*)d_in[0];
    const float* ln_w     = (const float*)d_in[1];
    const float* ln_b     = (const float*)d_in[2];
    const float* wqkv_w   = (const float*)d_in[3];
    const float* wqkv_b   = (const float*)d_in[4];
    const float* out_w    = (const float*)d_in[5];
    const float* out_b    = (const float*)d_in[6];
    const float* ffn_ln_w = (const float*)d_in[7];
    const float* ffn_ln_b = (const float*)d_in[8];
    const float* ff1_w    = (const float*)d_in[9];
    const float* ff1_b    = (const float*)d_in[10];
    const float* ff2_w    = (const float*)d_in[11];
    const float* ff2_b    = (const float*)d_in[12];
    float* out = (float*)d_out;

    __half *xln, *Q, *K, *V, *ctx, *hid, *wqkvh, *outwh, *ff1h, *ff2h;
    float *qkv, *src2;
    float2* tab;
    cudaGetSymbolAddress((void**)&xln,   g_xln_h);
    cudaGetSymbolAddress((void**)&qkv,   g_qkv);
    cudaGetSymbolAddress((void**)&Q,     g_Qh);
    cudaGetSymbolAddress((void**)&K,     g_Kh);
    cudaGetSymbolAddress((void**)&V,     g_Vh);
    cudaGetSymbolAddress((void**)&ctx,   g_ctx_h);
    cudaGetSymbolAddress((void**)&src2,  g_src2);
    cudaGetSymbolAddress((void**)&hid,   g_hid_h);
    cudaGetSymbolAddress((void**)&tab,   g_rope);
    cudaGetSymbolAddress((void**)&wqkvh, g_wqkv_h);
    cudaGetSymbolAddress((void**)&outwh, g_outw_h);
    cudaGetSymbolAddress((void**)&ff1h,  g_ff1_h);
    cudaGetSymbolAddress((void**)&ff2h,  g_ff2_h);

    cudaFuncSetAttribute(flash_h, cudaFuncAttributeMaxDynamicSharedMemorySize, FLASH_SMEM);

    // 0. convert weights to half
    f2h_kernel<<<(3*D_MODEL*D_MODEL/4 + 255)/256, 256>>>(wqkv_w, wqkvh, 3*D_MODEL*D_MODEL/4);
    f2h_kernel<<<(D_MODEL*D_MODEL/4   + 255)/256, 256>>>(out_w,  outwh, D_MODEL*D_MODEL/4);
    f2h_kernel<<<(D_FF*D_MODEL/4      + 255)/256, 256>>>(ff1_w,  ff1h,  D_FF*D_MODEL/4);
    f2h_kernel<<<(D_MODEL*D_FF/4      + 255)/256, 256>>>(ff2_w,  ff2h,  D_MODEL*D_FF/4);

    // 1. LN(src) -> half
    ln_kernel<<<ROWS, 128>>>(src, ln_w, ln_b, xln);
    // 2. QKV projection (fp16 wmma) -> fp32 qkv
    gemm_h<false, false, false><<<dim3(12, 64), 256>>>(xln, wqkvh, wqkv_b, nullptr,
                                                       qkv, nullptr, ROWS, 3*D_MODEL, D_MODEL);
    // 3. RoPE table + split -> half Q,K,V
    rope_tab_kernel<<<(SEQ * 32) / 256, 256>>>(tab);
    rope_split_kernel<<<(ROWS * 8 * 32) / 256, 256>>>(qkv, tab, Q, K, V);
    // 4. causal flash attention -> half ctx
    flash_h<<<dim3(SEQ / 64, BH), 256, FLASH_SMEM>>>(Q, K, V, ctx);
    // 5. out projection + residual -> fp32 src2
    gemm_h<false, true, false><<<dim3(4, 64), 256>>>(ctx, outwh, out_b, src,
                                                     src2, nullptr, ROWS, D_MODEL, D_MODEL);
    // 6. LN2 -> half
    ln_kernel<<<ROWS, 128>>>(src2, ffn_ln_w, ffn_ln_b, xln);
    // 7. FF1 + relu -> half hid
    gemm_h<true, false, true><<<dim3(16, 64), 256>>>(xln, ff1h, ff1_b, nullptr,
                                                     nullptr, hid, ROWS, D_FF, D_MODEL);
    // 8. FF2 + residual -> fp32 out
    gemm_h<false, true, false><<<dim3(4, 64), 256>>>(hid, ff2h, ff2_b, src2,
                                                     out, nullptr, ROWS, D_MODEL, D_FF);
}

// round 6
// speedup vs baseline: 4.5728x; 1.5061x over previous
#include <cuda_runtime.h>
#include <cuda_fp16.h>
#include <mma.h>
#include <math.h>

using namespace nvcuda;

#define D_MODEL 512
#define N_HEADS 8
#define HEAD_DIM 64
#define D_FF 2048
#define SEQ 4096
#define BATCH 2
#define ROWS (BATCH*SEQ)
#define BH (BATCH*N_HEADS)

// scratch buffers (no allocation allowed)
__device__ __half  g_xln_h [ROWS*D_MODEL];
__device__ float   g_qkv   [ROWS*3*D_MODEL];
__device__ __half  g_Qh    [BH*SEQ*HEAD_DIM];
__device__ __half  g_Kh    [BH*SEQ*HEAD_DIM];
__device__ __half  g_Vh    [BH*SEQ*HEAD_DIM];
__device__ __half  g_ctx_h [ROWS*D_MODEL];
__device__ float   g_src2  [ROWS*D_MODEL];
__device__ __half  g_hid_h [ROWS*D_FF];
__device__ float2  g_rope  [SEQ*32];
__device__ __half  g_wqkv_h[3*D_MODEL*D_MODEL];
__device__ __half  g_outw_h[D_MODEL*D_MODEL];
__device__ __half  g_ff1_h [D_FF*D_MODEL];
__device__ __half  g_ff2_h [D_MODEL*D_FF];

// asm macros
#define CP16(dst, src) \
    asm volatile("cp.async.cg.shared.global [%0], [%1], 16;" :: "r"(dst), "l"(src))
#define CPCOMMIT() asm volatile("cp.async.commit_group;")
#define CPWAIT0()  asm volatile("cp.async.wait_group 0;")
#define LDSM4(r0, r1, r2, r3, addr) \
    asm volatile("ldmatrix.sync.aligned.m8n8.x4.shared.b16 {%0,%1,%2,%3}, [%4];" \
                 : "=r"(r0), "=r"(r1), "=r"(r2), "=r"(r3) : "r"(addr))
#define LDSM4T(r0, r1, r2, r3, addr) \
    asm volatile("ldmatrix.sync.aligned.m8n8.x4.trans.shared.b16 {%0,%1,%2,%3}, [%4];" \
                 : "=r"(r0), "=r"(r1), "=r"(r2), "=r"(r3) : "r"(addr))
#define MMA168(c0, c1, c2, c3, a0, a1, a2, a3, b0, b1) \
    asm volatile("mma.sync.aligned.m16n8k16.row.col.f32.f16.f16.f32 " \
                 "{%0,%1,%2,%3},{%4,%5,%6,%7},{%8,%9},{%0,%1,%2,%3};" \
                 : "+f"(c0), "+f"(c1), "+f"(c2), "+f"(c3) \
                 : "r"(a0), "r"(a1), "r"(a2), "r"(a3), "r"(b0), "r"(b1))

__device__ __forceinline__ unsigned smem_u32(const void* p)
{
    return (unsigned)__cvta_generic_to_shared(p);
}
__device__ __forceinline__ unsigned pack_h2(float a, float b)
{
    __half2 h = __floats2half2_rn(a, b);
    return *reinterpret_cast<unsigned*>(&h);
}

// fp32 -> fp16 convert
__global__ void __launch_bounds__(256) f2h_kernel(const float* __restrict__ in,
                                                  __half* __restrict__ out, int n4)
{
    int i = blockIdx.x * 256 + threadIdx.x;
    if (i < n4) {
        float4 v = reinterpret_cast<const float4*>(in)[i];
        reinterpret_cast<__half2*>(out)[i * 2 + 0] = __floats2half2_rn(v.x, v.y);
        reinterpret_cast<__half2*>(out)[i * 2 + 1] = __floats2half2_rn(v.z, v.w);
    }
}

// LayerNorm, one block per row of 512, half output
__global__ void __launch_bounds__(128) ln_kernel(const float* __restrict__ x,
                                                 const float* __restrict__ w,
                                                 const float* __restrict__ b,
                                                 __half* __restrict__ y)
{
    int row = blockIdx.x;
    int t = threadIdx.x;
    const float4* xr = reinterpret_cast<const float4*>(x) + (size_t)row * 128;
    float4 v = xr[t];
    float s  = v.x + v.y + v.z + v.w;
    float ss = v.x*v.x + v.y*v.y + v.z*v.z + v.w*v.w;
    #pragma unroll
    for (int off = 16; off >= 1; off >>= 1) {
        s  += __shfl_xor_sync(0xffffffffu, s,  off);
        ss += __shfl_xor_sync(0xffffffffu, ss, off);
    }
    __shared__ float rs[4], rss[4];
    int wid = t >> 5;
    if ((t & 31) == 0) { rs[wid] = s; rss[wid] = ss; }
    __syncthreads();
    s  = rs[0] + rs[1] + rs[2] + rs[3];
    ss = rss[0] + rss[1] + rss[2] + rss[3];
    float mu  = s * (1.0f / 512.0f);
    float var = ss * (1.0f / 512.0f) - mu * mu;
    float r   = rsqrtf(var + 1e-5f);
    float4 w4 = reinterpret_cast<const float4*>(w)[t];
    float4 b4 = reinterpret_cast<const float4*>(b)[t];
    __half2* yr = reinterpret_cast<__half2*>(y) + (size_t)row * 256;
    yr[t * 2 + 0] = __floats2half2_rn((v.x - mu) * r * w4.x + b4.x,
                                      (v.y - mu) * r * w4.y + b4.y);
    yr[t * 2 + 1] = __floats2half2_rn((v.z - mu) * r * w4.z + b4.z,
                                      (v.w - mu) * r * w4.w + b4.w);
}

// fp16 wmma NT GEMM (same as round-3 passing version)
#define HLDA 40
template<bool RELU, bool RESID, bool OUTH>
__global__ void __launch_bounds__(256) gemm_h(const __half* __restrict__ A,
                                              const __half* __restrict__ W,
                                              const float* __restrict__ bias,
                                              const float* __restrict__ resid,
                                              float* __restrict__ C,
                                              __half* __restrict__ Ch,
                                              int M, int N, int K)
{
    __shared__ __half As[128 * HLDA];
    __shared__ __half Ws[128 * HLDA];
    int tid = threadIdx.x;
    int wid = tid >> 5;
    int lane = tid & 31;
    int wr = wid >> 1;
    int wc = wid & 1;
    int bm = blockIdx.y * 128;
    int bn = blockIdx.x * 128;

    wmma::fragment<wmma::accumulator, 16, 16, 16, float> acc[2][4];
    #pragma unroll
    for (int i = 0; i < 2; i++) {
        #pragma unroll
        for (int j = 0; j < 4; j++) {
            wmma::fill_fragment(acc[i][j], 0.0f);
        }
    }

    for (int k0 = 0; k0 < K; k0 += 32) {
        #pragma unroll
        for (int it = 0; it < 2; ++it) {
            int lin = tid + it * 256;
            int row = lin >> 2;
            int ch  = (lin & 3) * 8;
            *reinterpret_cast<int4*>(&As[row * HLDA + ch]) =
                *reinterpret_cast<const int4*>(&A[(size_t)(bm + row) * K + k0 + ch]);
            *reinterpret_cast<int4*>(&Ws[row * HLDA + ch]) =
                *reinterpret_cast<const int4*>(&W[(size_t)(bn + row) * K + k0 + ch]);
        }
        __syncthreads();
        #pragma unroll
        for (int ks = 0; ks < 2; ks++) {
            int k16 = ks * 16;
            wmma::fragment<wmma::matrix_a, 16, 16, 16, __half, wmma::row_major> af[2];
            #pragma unroll
            for (int i = 0; i < 2; i++) {
                wmma::load_matrix_sync(af[i], &As[(wr * 32 + i * 16) * HLDA + k16], HLDA);
            }
            wmma::fragment<wmma::matrix_b, 16, 16, 16, __half, wmma::col_major> bf[4];
            #pragma unroll
            for (int j = 0; j < 4; j++) {
                wmma::load_matrix_sync(bf[j], &Ws[(wc * 64 + j * 16) * HLDA + k16], HLDA);
            }
            #pragma unroll
            for (int i = 0; i < 2; i++) {
                #pragma unroll
                for (int j = 0; j < 4; j++) {
                    wmma::mma_sync(acc[i][j], af[i], bf[j], acc[i][j]);
                }
            }
        }
        __syncthreads();
    }

    float* cbuf = reinterpret_cast<float*>(As) + wid * 16 * 20;
    #pragma unroll
    for (int i = 0; i < 2; i++) {
        #pragma unroll
        for (int j = 0; j < 4; j++) {
            wmma::store_matrix_sync(cbuf, acc[i][j], 20, wmma::mem_row_major);
            __syncwarp();
            #pragma unroll
            for (int u = 0; u < 2; u++) {
                int e = lane + u * 32;
                int row = e >> 2;
                int c4 = (e & 3) * 4;
                float4 o = *reinterpret_cast<float4*>(&cbuf[row * 20 + c4]);
                int gr = bm + wr * 32 + i * 16 + row;
                int gc = bn + wc * 64 + j * 16 + c4;
                float4 bb = *reinterpret_cast<const float4*>(&bias[gc]);
                o.x += bb.x; o.y += bb.y; o.z += bb.z; o.w += bb.w;
                if (RELU) {
                    o.x = fmaxf(o.x, 0.0f); o.y = fmaxf(o.y, 0.0f);
                    o.z = fmaxf(o.z, 0.0f); o.w = fmaxf(o.w, 0.0f);
                }
                if (RESID) {
                    float4 rv = *reinterpret_cast<const float4*>(&resid[(size_t)gr * N + gc]);
                    o.x += rv.x; o.y += rv.y; o.z += rv.z; o.w += rv.w;
                }
                if (OUTH) {
                    *reinterpret_cast<__half2*>(&Ch[(size_t)gr * N + gc]) =
                        __floats2half2_rn(o.x, o.y);
                    *reinterpret_cast<__half2*>(&Ch[(size_t)gr * N + gc + 2]) =
                        __floats2half2_rn(o.z, o.w);
                } else {
                    *reinterpret_cast<float4*>(&C[(size_t)gr * N + gc]) = o;
                }
            }
            __syncwarp();
        }
    }
}

// RoPE table
__global__ void __launch_bounds__(256) rope_tab_kernel(float2* __restrict__ tab)
{
    int idx = blockIdx.x * 256 + threadIdx.x;
    int s = idx >> 5;
    int i = idx & 31;
    double freq = 1.0 / pow(10000.0, (double)i / 32.0);
    float ang = (float)((double)s * freq);
    tab[idx] = make_float2(cosf(ang), sinf(ang));
}

// split fp32 qkv into half Q (rope, prescaled), K (rope), V with layout [B,H,S,D]
__global__ void __launch_bounds__(256) rope_split_kernel(const float* __restrict__ qkv,
                                                         const float2* __restrict__ tab,
                                                         __half* __restrict__ Q,
                                                         __half* __restrict__ K,
                                                         __half* __restrict__ V)
{
    int idx = blockIdx.x * 256 + threadIdx.x;
    int d2 = idx & 31;
    int hh = (idx >> 5) & 7;
    int bs = idx >> 8;
    int s  = bs & (SEQ - 1);
    int b  = bs >> 12;
    const float* base = qkv + (size_t)bs * 1536 + hh * 64 + d2 * 2;
    float2 q = *reinterpret_cast<const float2*>(base);
    float2 k = *reinterpret_cast<const float2*>(base + 512);
    float2 v = *reinterpret_cast<const float2*>(base + 1024);
    float2 cs = tab[s * 32 + d2];
    size_t o = ((((size_t)b * 8 + hh) * SEQ) + s) * 64 + d2 * 2;
    const float sc = 0.125f;
    reinterpret_cast<__half2*>(Q)[o >> 1] =
        __floats2half2_rn((q.x * cs.x - q.y * cs.y) * sc, (q.x * cs.y + q.y * cs.x) * sc);
    reinterpret_cast<__half2*>(K)[o >> 1] =
        __floats2half2_rn(k.x * cs.x - k.y * cs.y, k.x * cs.y + k.y * cs.x);
    reinterpret_cast<__half2*>(V)[o >> 1] = __floats2half2_rn(v.x, v.y);
}

// register-resident causal flash attention
// 128 threads, 4 warps, Q tile 64 (16 rows per warp), KV tile 64, head dim 64.
// smem tiles: 64 rows x 128 bytes, 16B chunk c stored at (c xor (row and 7)).
__global__ void __launch_bounds__(128) flash_mma(const __half* __restrict__ Qg,
                                                 const __half* __restrict__ Kg,
                                                 const __half* __restrict__ Vg,
                                                 __half* __restrict__ ctx)
{
    __shared__ __half sQ[4096];
    __shared__ __half sK0[4096];
    __shared__ __half sK1[4096];
    __shared__ __half sV0[4096];
    __shared__ __half sV1[4096];

    int qt = (int)gridDim.x - 1 - blockIdx.x;
    int bh = blockIdx.y;
    int bb = bh >> 3;
    int hh = bh & 7;
    const __half* Qb = Qg + ((size_t)bh * SEQ + qt * 64) * 64;
    const __half* Kb = Kg + (size_t)bh * SEQ * 64;
    const __half* Vb = Vg + (size_t)bh * SEQ * 64;

    int tid = threadIdx.x;
    int lane = tid & 31;
    int wq = tid >> 5;
    int lr = lane & 7;
    int lg = lane >> 3;
    unsigned aQ = smem_u32(sQ);
    unsigned aK0 = smem_u32(sK0);
    unsigned aK1 = smem_u32(sK1);
    unsigned aV0 = smem_u32(sV0);
    unsigned aV1 = smem_u32(sV1);

    // initial loads: Q tile, first K tile, first V tile
    {
        int r = tid >> 1;
        int cbase = (tid & 1) * 4;
        #pragma unroll
        for (int c = cbase; c < cbase + 4; c++) {
            CP16(aQ  + r * 128 + ((c ^ (r & 7)) << 4), Qb + r * 64 + c * 8);
            CP16(aK0 + r * 128 + ((c ^ (r & 7)) << 4), Kb + r * 64 + c * 8);
            CP16(aV0 + r * 128 + ((c ^ (r & 7)) << 4), Vb + r * 64 + c * 8);
        }
    }
    CPCOMMIT();
    CPWAIT0();
    __syncthreads();

    // Q fragments (held for the whole kernel)
    unsigned qa[4][4];
    #pragma unroll
    for (int kc = 0; kc < 4; kc++) {
        int qrow = wq * 16 + ((lg & 1) << 3) + lr;
        int qch  = kc * 2 + (lg >> 1);
        LDSM4(qa[kc][0], qa[kc][1], qa[kc][2], qa[kc][3],
              aQ + qrow * 128 + ((qch ^ (qrow & 7)) << 4));
    }

    float O[8][4];
    #pragma unroll
    for (int j = 0; j < 8; j++) {
        O[j][0] = 0.0f; O[j][1] = 0.0f; O[j][2] = 0.0f; O[j][3] = 0.0f;
    }
    float m1 = -1e30f;
    float m2 = -1e30f;
    float l1 = 0.0f;
    float l2 = 0.0f;

    int grow1 = qt * 64 + wq * 16 + (lane >> 2);
    int grow2 = grow1 + 8;

    for (int kt = 0; kt <= qt; ++kt) {
        unsigned curK = (kt & 1) ? aK1 : aK0;
        unsigned curV = (kt & 1) ? aV1 : aV0;
        unsigned nxtK = (kt & 1) ? aK0 : aK1;
        unsigned nxtV = (kt & 1) ? aV0 : aV1;
        if (kt < qt) {
            const __half* Kn = Kb + (size_t)(kt + 1) * 4096;
            const __half* Vn = Vb + (size_t)(kt + 1) * 4096;
            int r = tid >> 1;
            int cbase = (tid & 1) * 4;
            #pragma unroll
            for (int c = cbase; c < cbase + 4; c++) {
                CP16(nxtK + r * 128 + ((c ^ (r & 7)) << 4), Kn + r * 64 + c * 8);
                CP16(nxtV + r * 128 + ((c ^ (r & 7)) << 4), Vn + r * 64 + c * 8);
            }
            CPCOMMIT();
        }

        // S = Q * K^T
        float S[8][4];
        #pragma unroll
        for (int j = 0; j < 8; j++) {
            S[j][0] = 0.0f; S[j][1] = 0.0f; S[j][2] = 0.0f; S[j][3] = 0.0f;
        }
        #pragma unroll
        for (int ng = 0; ng < 4; ng++) {
            #pragma unroll
            for (int kc = 0; kc < 4; kc++) {
                int krow = ng * 16 + ((lg >> 1) << 3) + lr;
                int kch  = kc * 2 + (lg & 1);
                unsigned b0, b1, b2, b3;
                LDSM4(b0, b1, b2, b3, curK + krow * 128 + ((kch ^ (krow & 7)) << 4));
                MMA168(S[ng * 2][0], S[ng * 2][1], S[ng * 2][2], S[ng * 2][3],
                       qa[kc][0], qa[kc][1], qa[kc][2], qa[kc][3], b0, b1);
                MMA168(S[ng * 2 + 1][0], S[ng * 2 + 1][1], S[ng * 2 + 1][2], S[ng * 2 + 1][3],
                       qa[kc][0], qa[kc][1], qa[kc][2], qa[kc][3], b2, b3);
            }
        }

        // causal mask on the diagonal tile
        if (kt == qt) {
            #pragma unroll
            for (int j = 0; j < 8; j++) {
                int col = kt * 64 + j * 8 + (lane & 3) * 2;
                if (col     > grow1) S[j][0] = -1e30f;
                if (col + 1 > grow1) S[j][1] = -1e30f;
                if (col     > grow2) S[j][2] = -1e30f;
                if (col + 1 > grow2) S[j][3] = -1e30f;
            }
        }

        // online softmax in registers (reduce across 4-lane quad)
        float mx1 = -1e30f;
        float mx2 = -1e30f;
        #pragma unroll
        for (int j = 0; j < 8; j++) {
            mx1 = fmaxf(mx1, fmaxf(S[j][0], S[j][1]));
            mx2 = fmaxf(mx2, fmaxf(S[j][2], S[j][3]));
        }
        mx1 = fmaxf(mx1, __shfl_xor_sync(0xffffffffu, mx1, 1));
        mx1 = fmaxf(mx1, __shfl_xor_sync(0xffffffffu, mx1, 2));
        mx2 = fmaxf(mx2, __shfl_xor_sync(0xffffffffu, mx2, 1));
        mx2 = fmaxf(mx2, __shfl_xor_sync(0xffffffffu, mx2, 2));
        float mn1 = fmaxf(m1, mx1);
        float mn2 = fmaxf(m2, mx2);
        float al1 = __expf(m1 - mn1);
        float al2 = __expf(m2 - mn2);
        float sm1 = 0.0f;
        float sm2 = 0.0f;
        #pragma unroll
        for (int j = 0; j < 8; j++) {
            S[j][0] = __expf(S[j][0] - mn1);
            S[j][1] = __expf(S[j][1] - mn1);
            S[j][2] = __expf(S[j][2] - mn2);
            S[j][3] = __expf(S[j][3] - mn2);
            sm1 += S[j][0] + S[j][1];
            sm2 += S[j][2] + S[j][3];
        }
        sm1 += __shfl_xor_sync(0xffffffffu, sm1, 1);
        sm1 += __shfl_xor_sync(0xffffffffu, sm1, 2);
        sm2 += __shfl_xor_sync(0xffffffffu, sm2, 1);
        sm2 += __shfl_xor_sync(0xffffffffu, sm2, 2);
        l1 = l1 * al1 + sm1;
        l2 = l2 * al2 + sm2;
        m1 = mn1;
        m2 = mn2;
        #pragma unroll
        for (int j = 0; j < 8; j++) {
            O[j][0] *= al1; O[j][1] *= al1;
            O[j][2] *= al2; O[j][3] *= al2;
        }

        // pack P fragments from S
        unsigned pa[4][4];
        #pragma unroll
        for (int kc = 0; kc < 4; kc++) {
            pa[kc][0] = pack_h2(S[2 * kc][0],     S[2 * kc][1]);
            pa[kc][1] = pack_h2(S[2 * kc][2],     S[2 * kc][3]);
            pa[kc][2] = pack_h2(S[2 * kc + 1][0], S[2 * kc + 1][1]);
            pa[kc][3] = pack_h2(S[2 * kc + 1][2], S[2 * kc + 1][3]);
        }

        // O += P * V
        #pragma unroll
        for (int dg = 0; dg < 4; dg++) {
            #pragma unroll
            for (int tc = 0; tc < 4; tc++) {
                int vrow = tc * 16 + ((lg & 1) << 3) + lr;
                int vch  = dg * 2 + (lg >> 1);
                unsigned v0, v1, v2, v3;
                LDSM4T(v0, v1, v2, v3, curV + vrow * 128 + ((vch ^ (vrow & 7)) << 4));
                MMA168(O[dg * 2][0], O[dg * 2][1], O[dg * 2][2], O[dg * 2][3],
                       pa[tc][0], pa[tc][1], pa[tc][2], pa[tc][3], v0, v1);
                MMA168(O[dg * 2 + 1][0], O[dg * 2 + 1][1], O[dg * 2 + 1][2], O[dg * 2 + 1][3],
                       pa[tc][0], pa[tc][1], pa[tc][2], pa[tc][3], v2, v3);
            }
        }

        if (kt < qt) {
            CPWAIT0();
            __syncthreads();
        }
    }

    // finalize: ctx[b][s][h*64+d] = O / l
    float inv1 = 1.0f / l1;
    float inv2 = 1.0f / l2;
    size_t base1 = ((size_t)bb * SEQ + grow1) * 512 + hh * 64;
    size_t base2 = ((size_t)bb * SEQ + grow2) * 512 + hh * 64;
    #pragma unroll
    for (int j = 0; j < 8; j++) {
        int col = j * 8 + (lane & 3) * 2;
        *reinterpret_cast<__half2*>(&ctx[base1 + col]) =
            __floats2half2_rn(O[j][0] * inv1, O[j][1] * inv1);
        *reinterpret_cast<__half2*>(&ctx[base2 + col]) =
            __floats2half2_rn(O[j][2] * inv2, O[j][3] * inv2);
    }
}

extern "C" void kernel_launch(void* const* d_in, const int* in_sizes, int n_in,
                              void* d_out, int out_size)
{
    const float* src      = (const float*)d_in[0];
    const float* ln_w     = (const float*)d_in[1];
    const float* ln_b     = (const float*)d_in[2];
    const float* wqkv_w   = (const float*)d_in[3];
    const float* wqkv_b   = (const float*)d_in[4];
    const float* out_w    = (const float*)d_in[5];
    const float* out_b    = (const float*)d_in[6];
    const float* ffn_ln_w = (const float*)d_in[7];
    const float* ffn_ln_b = (const float*)d_in[8];
    const float* ff1_w    = (const float*)d_in[9];
    const float* ff1_b    = (const float*)d_in[10];
    const float* ff2_w    = (const float*)d_in[11];
    const float* ff2_b    = (const float*)d_in[12];
    float* out = (float*)d_out;

    __half *xln, *Q, *K, *V, *ctx, *hid, *wqkvh, *outwh, *ff1h, *ff2h;
    float *qkv, *src2;
    float2* tab;
    cudaGetSymbolAddress((void**)&xln,   g_xln_h);
    cudaGetSymbolAddress((void**)&qkv,   g_qkv);
    cudaGetSymbolAddress((void**)&Q,     g_Qh);
    cudaGetSymbolAddress((void**)&K,     g_Kh);
    cudaGetSymbolAddress((void**)&V,     g_Vh);
    cudaGetSymbolAddress((void**)&ctx,   g_ctx_h);
    cudaGetSymbolAddress((void**)&src2,  g_src2);
    cudaGetSymbolAddress((void**)&hid,   g_hid_h);
    cudaGetSymbolAddress((void**)&tab,   g_rope);
    cudaGetSymbolAddress((void**)&wqkvh, g_wqkv_h);
    cudaGetSymbolAddress((void**)&outwh, g_outw_h);
    cudaGetSymbolAddress((void**)&ff1h,  g_ff1_h);
    cudaGetSymbolAddress((void**)&ff2h,  g_ff2_h);

    f2h_kernel<<<(3*D_MODEL*D_MODEL/4 + 255)/256, 256>>>(wqkv_w, wqkvh, 3*D_MODEL*D_MODEL/4);
    f2h_kernel<<<(D_MODEL*D_MODEL/4   + 255)/256, 256>>>(out_w,  outwh, D_MODEL*D_MODEL/4);
    f2h_kernel<<<(D_FF*D_MODEL/4      + 255)/256, 256>>>(ff1_w,  ff1h,  D_FF*D_MODEL/4);
    f2h_kernel<<<(D_MODEL*D_FF/4      + 255)/256, 256>>>(ff2_w,  ff2h,  D_MODEL*D_FF/4);

    ln_kernel<<<ROWS, 128>>>(src, ln_w, ln_b, xln);
    gemm_h<false, false, false><<<dim3(12, 64), 256>>>(xln, wqkvh, wqkv_b, nullptr,
                                                       qkv, nullptr, ROWS, 3*D_MODEL, D_MODEL);
    rope_tab_kernel<<<(SEQ * 32) / 256, 256>>>(tab);
    rope_split_kernel<<<(ROWS * 8 * 32) / 256, 256>>>(qkv, tab, Q, K, V);
    flash_mma<<<dim3(SEQ / 64, BH), 128>>>(Q, K, V, ctx);
    gemm_h<false, true, false><<<dim3(4, 64), 256>>>(ctx, outwh, out_b, src,
                                                     src2, nullptr, ROWS, D_MODEL, D_MODEL);
    ln_kernel<<<ROWS, 128>>>(src2, ffn_ln_w, ffn_ln_b, xln);
    gemm_h<true, false, true><<<dim3(16, 64), 256>>>(xln, ff1h, ff1_b, nullptr,
                                                     nullptr, hid, ROWS, D_FF, D_MODEL);
    gemm_h<false, true, false><<<dim3(4, 64), 256>>>(hid, ff2h, ff2_b, src2,
                                                     out, nullptr, ROWS, D_MODEL, D_FF);
}

// round 7
// speedup vs baseline: 5.0698x; 1.1087x over previous
#include <cuda_runtime.h>
#include <cuda_fp16.h>
#include <mma.h>
#include <math.h>

using namespace nvcuda;

#define D_MODEL 512
#define N_HEADS 8
#define HEAD_DIM 64
#define D_FF 2048
#define SEQ 4096
#define BATCH 2
#define ROWS (BATCH*SEQ)
#define BH (BATCH*N_HEADS)

// scratch buffers (no allocation allowed)
__device__ __half  g_xln_h [ROWS*D_MODEL];
__device__ __half  g_qkv_h [ROWS*3*D_MODEL];
__device__ __half  g_Qh    [BH*SEQ*HEAD_DIM];
__device__ __half  g_Kh    [BH*SEQ*HEAD_DIM];
__device__ __half  g_Vh    [BH*SEQ*HEAD_DIM];
__device__ __half  g_ctx_h [ROWS*D_MODEL];
__device__ float   g_src2  [ROWS*D_MODEL];
__device__ __half  g_hid_h [ROWS*D_FF];
__device__ float2  g_rope  [SEQ*32];
__device__ __half  g_wqkv_h[3*D_MODEL*D_MODEL];
__device__ __half  g_outw_h[D_MODEL*D_MODEL];
__device__ __half  g_ff1_h [D_FF*D_MODEL];
__device__ __half  g_ff2_h [D_MODEL*D_FF];

// asm macros
#define CP16(dst, src) \
    asm volatile("cp.async.cg.shared.global [%0], [%1], 16;" :: "r"(dst), "l"(src))
#define CPCOMMIT() asm volatile("cp.async.commit_group;")
#define CPWAIT0()  asm volatile("cp.async.wait_group 0;")
#define CPWAIT1()  asm volatile("cp.async.wait_group 1;")
#define LDSM4(r0, r1, r2, r3, addr) \
    asm volatile("ldmatrix.sync.aligned.m8n8.x4.shared.b16 {%0,%1,%2,%3}, [%4];" \
                 : "=r"(r0), "=r"(r1), "=r"(r2), "=r"(r3) : "r"(addr))
#define LDSM4T(r0, r1, r2, r3, addr) \
    asm volatile("ldmatrix.sync.aligned.m8n8.x4.trans.shared.b16 {%0,%1,%2,%3}, [%4];" \
                 : "=r"(r0), "=r"(r1), "=r"(r2), "=r"(r3) : "r"(addr))
#define MMA168(c0, c1, c2, c3, a0, a1, a2, a3, b0, b1) \
    asm volatile("mma.sync.aligned.m16n8k16.row.col.f32.f16.f16.f32 " \
                 "{%0,%1,%2,%3},{%4,%5,%6,%7},{%8,%9},{%0,%1,%2,%3};" \
                 : "+f"(c0), "+f"(c1), "+f"(c2), "+f"(c3) \
                 : "r"(a0), "r"(a1), "r"(a2), "r"(a3), "r"(b0), "r"(b1))

__device__ __forceinline__ unsigned smem_u32(const void* p)
{
    return (unsigned)__cvta_generic_to_shared(p);
}
__device__ __forceinline__ unsigned pack_h2(float a, float b)
{
    __half2 h = __floats2half2_rn(a, b);
    return *reinterpret_cast<unsigned*>(&h);
}

// fused fp32 -> fp16 for all four weight tensors
#define N4_QKV (3*D_MODEL*D_MODEL/4)
#define N4_OUT (D_MODEL*D_MODEL/4)
#define N4_FF1 (D_FF*D_MODEL/4)
#define N4_FF2 (D_MODEL*D_FF/4)
__global__ void __launch_bounds__(256) f2h_all(const float* __restrict__ w0,
                                               const float* __restrict__ w1,
                                               const float* __restrict__ w2,
                                               const float* __restrict__ w3,
                                               __half* __restrict__ o0,
                                               __half* __restrict__ o1,
                                               __half* __restrict__ o2,
                                               __half* __restrict__ o3)
{
    int i = blockIdx.x * 256 + threadIdx.x;
    const float* in;
    __half* out;
    int k;
    if (i < N4_QKV) {
        in = w0; out = o0; k = i;
    } else if (i < N4_QKV + N4_OUT) {
        in = w1; out = o1; k = i - N4_QKV;
    } else if (i < N4_QKV + N4_OUT + N4_FF1) {
        in = w2; out = o2; k = i - N4_QKV - N4_OUT;
    } else if (i < N4_QKV + N4_OUT + N4_FF1 + N4_FF2) {
        in = w3; out = o3; k = i - N4_QKV - N4_OUT - N4_FF1;
    } else {
        return;
    }
    float4 v = reinterpret_cast<const float4*>(in)[k];
    reinterpret_cast<__half2*>(out)[k * 2 + 0] = __floats2half2_rn(v.x, v.y);
    reinterpret_cast<__half2*>(out)[k * 2 + 1] = __floats2half2_rn(v.z, v.w);
}

// LayerNorm, one block per row of 512, half output
__global__ void __launch_bounds__(128) ln_kernel(const float* __restrict__ x,
                                                 const float* __restrict__ w,
                                                 const float* __restrict__ b,
                                                 __half* __restrict__ y)
{
    int row = blockIdx.x;
    int t = threadIdx.x;
    const float4* xr = reinterpret_cast<const float4*>(x) + (size_t)row * 128;
    float4 v = xr[t];
    float s  = v.x + v.y + v.z + v.w;
    float ss = v.x*v.x + v.y*v.y + v.z*v.z + v.w*v.w;
    #pragma unroll
    for (int off = 16; off >= 1; off >>= 1) {
        s  += __shfl_xor_sync(0xffffffffu, s,  off);
        ss += __shfl_xor_sync(0xffffffffu, ss, off);
    }
    __shared__ float rs[4], rss[4];
    int wid = t >> 5;
    if ((t & 31) == 0) { rs[wid] = s; rss[wid] = ss; }
    __syncthreads();
    s  = rs[0] + rs[1] + rs[2] + rs[3];
    ss = rss[0] + rss[1] + rss[2] + rss[3];
    float mu  = s * (1.0f / 512.0f);
    float var = ss * (1.0f / 512.0f) - mu * mu;
    float r   = rsqrtf(var + 1e-5f);
    float4 w4 = reinterpret_cast<const float4*>(w)[t];
    float4 b4 = reinterpret_cast<const float4*>(b)[t];
    __half2* yr = reinterpret_cast<__half2*>(y) + (size_t)row * 256;
    yr[t * 2 + 0] = __floats2half2_rn((v.x - mu) * r * w4.x + b4.x,
                                      (v.y - mu) * r * w4.y + b4.y);
    yr[t * 2 + 1] = __floats2half2_rn((v.z - mu) * r * w4.z + b4.z,
                                      (v.w - mu) * r * w4.w + b4.w);
}

// fp16 wmma NT GEMM with cp.async double buffering
#define HLDA 40
template<bool RELU, bool RESID, bool OUTH>
__global__ void __launch_bounds__(256) gemm_cp(const __half* __restrict__ A,
                                               const __half* __restrict__ W,
                                               const float* __restrict__ bias,
                                               const float* __restrict__ resid,
                                               float* __restrict__ C,
                                               __half* __restrict__ Ch,
                                               int M, int N, int K)
{
    __shared__ __half As0[128 * HLDA];
    __shared__ __half As1[128 * HLDA];
    __shared__ __half Ws0[128 * HLDA];
    __shared__ __half Ws1[128 * HLDA];
    int tid = threadIdx.x;
    int wid = tid >> 5;
    int lane = tid & 31;
    int wr = wid >> 1;
    int wc = wid & 1;
    int bm = blockIdx.y * 128;
    int bn = blockIdx.x * 128;
    int nK = K >> 5;

    // per-thread load slots: 2 chunks of A + 2 chunks of W per stage
    int ldrow0 = tid >> 2;
    int ldc0   = tid & 3;
    int ldrow1 = (tid + 256) >> 2;
    int ldc1   = (tid + 256) & 3;
    const __half* gA0 = A + (size_t)(bm + ldrow0) * K + ldc0 * 8;
    const __half* gA1 = A + (size_t)(bm + ldrow1) * K + ldc1 * 8;
    const __half* gW0 = W + (size_t)(bn + ldrow0) * K + ldc0 * 8;
    const __half* gW1 = W + (size_t)(bn + ldrow1) * K + ldc1 * 8;
    unsigned sA0c0 = smem_u32(As0) + (ldrow0 * HLDA + ldc0 * 8) * 2;
    unsigned sA0c1 = smem_u32(As0) + (ldrow1 * HLDA + ldc1 * 8) * 2;
    unsigned sA1c0 = smem_u32(As1) + (ldrow0 * HLDA + ldc0 * 8) * 2;
    unsigned sA1c1 = smem_u32(As1) + (ldrow1 * HLDA + ldc1 * 8) * 2;
    unsigned sW0c0 = smem_u32(Ws0) + (ldrow0 * HLDA + ldc0 * 8) * 2;
    unsigned sW0c1 = smem_u32(Ws0) + (ldrow1 * HLDA + ldc1 * 8) * 2;
    unsigned sW1c0 = smem_u32(Ws1) + (ldrow0 * HLDA + ldc0 * 8) * 2;
    unsigned sW1c1 = smem_u32(Ws1) + (ldrow1 * HLDA + ldc1 * 8) * 2;

    wmma::fragment<wmma::accumulator, 16, 16, 16, float> acc[2][4];
    #pragma unroll
    for (int i = 0; i < 2; i++) {
        #pragma unroll
        for (int j = 0; j < 4; j++) {
            wmma::fill_fragment(acc[i][j], 0.0f);
        }
    }

    // prologue: stage 0
    CP16(sA0c0, gA0);
    CP16(sA0c1, gA1);
    CP16(sW0c0, gW0);
    CP16(sW0c1, gW1);
    CPCOMMIT();

    for (int kt = 0; kt < nK; kt++) {
        int st = kt & 1;
        if (kt + 1 < nK) {
            int koff = (kt + 1) * 32;
            if (st == 0) {
                CP16(sA1c0, gA0 + koff);
                CP16(sA1c1, gA1 + koff);
                CP16(sW1c0, gW0 + koff);
                CP16(sW1c1, gW1 + koff);
            } else {
                CP16(sA0c0, gA0 + koff);
                CP16(sA0c1, gA1 + koff);
                CP16(sW0c0, gW0 + koff);
                CP16(sW0c1, gW1 + koff);
            }
            CPCOMMIT();
            CPWAIT1();
        } else {
            CPWAIT0();
        }
        __syncthreads();
        const __half* Asc = (st == 0) ? As0 : As1;
        const __half* Wsc = (st == 0) ? Ws0 : Ws1;
        #pragma unroll
        for (int ks = 0; ks < 2; ks++) {
            int k16 = ks * 16;
            wmma::fragment<wmma::matrix_a, 16, 16, 16, __half, wmma::row_major> af[2];
            #pragma unroll
            for (int i = 0; i < 2; i++) {
                wmma::load_matrix_sync(af[i], &Asc[(wr * 32 + i * 16) * HLDA + k16], HLDA);
            }
            wmma::fragment<wmma::matrix_b, 16, 16, 16, __half, wmma::col_major> bf[4];
            #pragma unroll
            for (int j = 0; j < 4; j++) {
                wmma::load_matrix_sync(bf[j], &Wsc[(wc * 64 + j * 16) * HLDA + k16], HLDA);
            }
            #pragma unroll
            for (int i = 0; i < 2; i++) {
                #pragma unroll
                for (int j = 0; j < 4; j++) {
                    wmma::mma_sync(acc[i][j], af[i], bf[j], acc[i][j]);
                }
            }
        }
        __syncthreads();
    }

    float* cbuf = reinterpret_cast<float*>(As0) + wid * 16 * 20;
    #pragma unroll
    for (int i = 0; i < 2; i++) {
        #pragma unroll
        for (int j = 0; j < 4; j++) {
            wmma::store_matrix_sync(cbuf, acc[i][j], 20, wmma::mem_row_major);
            __syncwarp();
            #pragma unroll
            for (int u = 0; u < 2; u++) {
                int e = lane + u * 32;
                int row = e >> 2;
                int c4 = (e & 3) * 4;
                float4 o = *reinterpret_cast<float4*>(&cbuf[row * 20 + c4]);
                int gr = bm + wr * 32 + i * 16 + row;
                int gc = bn + wc * 64 + j * 16 + c4;
                float4 bb = *reinterpret_cast<const float4*>(&bias[gc]);
                o.x += bb.x; o.y += bb.y; o.z += bb.z; o.w += bb.w;
                if (RELU) {
                    o.x = fmaxf(o.x, 0.0f); o.y = fmaxf(o.y, 0.0f);
                    o.z = fmaxf(o.z, 0.0f); o.w = fmaxf(o.w, 0.0f);
                }
                if (RESID) {
                    float4 rv = *reinterpret_cast<const float4*>(&resid[(size_t)gr * N + gc]);
                    o.x += rv.x; o.y += rv.y; o.z += rv.z; o.w += rv.w;
                }
                if (OUTH) {
                    *reinterpret_cast<__half2*>(&Ch[(size_t)gr * N + gc]) =
                        __floats2half2_rn(o.x, o.y);
                    *reinterpret_cast<__half2*>(&Ch[(size_t)gr * N + gc + 2]) =
                        __floats2half2_rn(o.z, o.w);
                } else {
                    *reinterpret_cast<float4*>(&C[(size_t)gr * N + gc]) = o;
                }
            }
            __syncwarp();
        }
    }
}

// RoPE table
__global__ void __launch_bounds__(256) rope_tab_kernel(float2* __restrict__ tab)
{
    int idx = blockIdx.x * 256 + threadIdx.x;
    int s = idx >> 5;
    int i = idx & 31;
    double freq = 1.0 / pow(10000.0, (double)i / 32.0);
    float ang = (float)((double)s * freq);
    tab[idx] = make_float2(cosf(ang), sinf(ang));
}

// split half qkv into half Q (rope, prescaled), K (rope), V with layout [B,H,S,D]
__global__ void __launch_bounds__(256) rope_split_kernel(const __half* __restrict__ qkv,
                                                         const float2* __restrict__ tab,
                                                         __half* __restrict__ Q,
                                                         __half* __restrict__ K,
                                                         __half* __restrict__ V)
{
    int idx = blockIdx.x * 256 + threadIdx.x;
    int d2 = idx & 31;
    int hh = (idx >> 5) & 7;
    int bs = idx >> 8;
    int s  = bs & (SEQ - 1);
    int b  = bs >> 12;
    const __half* base = qkv + (size_t)bs * 1536 + hh * 64 + d2 * 2;
    float2 q = __half22float2(*reinterpret_cast<const __half2*>(base));
    float2 k = __half22float2(*reinterpret_cast<const __half2*>(base + 512));
    __half2 v = *reinterpret_cast<const __half2*>(base + 1024);
    float2 cs = tab[s * 32 + d2];
    size_t o = ((((size_t)b * 8 + hh) * SEQ) + s) * 64 + d2 * 2;
    const float sc = 0.125f;
    reinterpret_cast<__half2*>(Q)[o >> 1] =
        __floats2half2_rn((q.x * cs.x - q.y * cs.y) * sc, (q.x * cs.y + q.y * cs.x) * sc);
    reinterpret_cast<__half2*>(K)[o >> 1] =
        __floats2half2_rn(k.x * cs.x - k.y * cs.y, k.x * cs.y + k.y * cs.x);
    reinterpret_cast<__half2*>(V)[o >> 1] = v;
}

// register-resident causal flash attention (identical to round-6 passing version)
__global__ void __launch_bounds__(128) flash_mma(const __half* __restrict__ Qg,
                                                 const __half* __restrict__ Kg,
                                                 const __half* __restrict__ Vg,
                                                 __half* __restrict__ ctx)
{
    __shared__ __half sQ[4096];
    __shared__ __half sK0[4096];
    __shared__ __half sK1[4096];
    __shared__ __half sV0[4096];
    __shared__ __half sV1[4096];

    int qt = (int)gridDim.x - 1 - blockIdx.x;
    int bh = blockIdx.y;
    int bb = bh >> 3;
    int hh = bh & 7;
    const __half* Qb = Qg + ((size_t)bh * SEQ + qt * 64) * 64;
    const __half* Kb = Kg + (size_t)bh * SEQ * 64;
    const __half* Vb = Vg + (size_t)bh * SEQ * 64;

    int tid = threadIdx.x;
    int lane = tid & 31;
    int wq = tid >> 5;
    int lr = lane & 7;
    int lg = lane >> 3;
    unsigned aQ = smem_u32(sQ);
    unsigned aK0 = smem_u32(sK0);
    unsigned aK1 = smem_u32(sK1);
    unsigned aV0 = smem_u32(sV0);
    unsigned aV1 = smem_u32(sV1);

    {
        int r = tid >> 1;
        int cbase = (tid & 1) * 4;
        #pragma unroll
        for (int c = cbase; c < cbase + 4; c++) {
            CP16(aQ  + r * 128 + ((c ^ (r & 7)) << 4), Qb + r * 64 + c * 8);
            CP16(aK0 + r * 128 + ((c ^ (r & 7)) << 4), Kb + r * 64 + c * 8);
            CP16(aV0 + r * 128 + ((c ^ (r & 7)) << 4), Vb + r * 64 + c * 8);
        }
    }
    CPCOMMIT();
    CPWAIT0();
    __syncthreads();

    unsigned qa[4][4];
    #pragma unroll
    for (int kc = 0; kc < 4; kc++) {
        int qrow = wq * 16 + ((lg & 1) << 3) + lr;
        int qch  = kc * 2 + (lg >> 1);
        LDSM4(qa[kc][0], qa[kc][1], qa[kc][2], qa[kc][3],
              aQ + qrow * 128 + ((qch ^ (qrow & 7)) << 4));
    }

    float O[8][4];
    #pragma unroll
    for (int j = 0; j < 8; j++) {
        O[j][0] = 0.0f; O[j][1] = 0.0f; O[j][2] = 0.0f; O[j][3] = 0.0f;
    }
    float m1 = -1e30f;
    float m2 = -1e30f;
    float l1 = 0.0f;
    float l2 = 0.0f;

    int grow1 = qt * 64 + wq * 16 + (lane >> 2);
    int grow2 = grow1 + 8;

    for (int kt = 0; kt <= qt; ++kt) {
        unsigned curK = (kt & 1) ? aK1 : aK0;
        unsigned curV = (kt & 1) ? aV1 : aV0;
        unsigned nxtK = (kt & 1) ? aK0 : aK1;
        unsigned nxtV = (kt & 1) ? aV0 : aV1;
        if (kt < qt) {
            const __half* Kn = Kb + (size_t)(kt + 1) * 4096;
            const __half* Vn = Vb + (size_t)(kt + 1) * 4096;
            int r = tid >> 1;
            int cbase = (tid & 1) * 4;
            #pragma unroll
            for (int c = cbase; c < cbase + 4; c++) {
                CP16(nxtK + r * 128 + ((c ^ (r & 7)) << 4), Kn + r * 64 + c * 8);
                CP16(nxtV + r * 128 + ((c ^ (r & 7)) << 4), Vn + r * 64 + c * 8);
            }
            CPCOMMIT();
        }

        float S[8][4];
        #pragma unroll
        for (int j = 0; j < 8; j++) {
            S[j][0] = 0.0f; S[j][1] = 0.0f; S[j][2] = 0.0f; S[j][3] = 0.0f;
        }
        #pragma unroll
        for (int ng = 0; ng < 4; ng++) {
            #pragma unroll
            for (int kc = 0; kc < 4; kc++) {
                int krow = ng * 16 + ((lg >> 1) << 3) + lr;
                int kch  = kc * 2 + (lg & 1);
                unsigned b0, b1, b2, b3;
                LDSM4(b0, b1, b2, b3, curK + krow * 128 + ((kch ^ (krow & 7)) << 4));
                MMA168(S[ng * 2][0], S[ng * 2][1], S[ng * 2][2], S[ng * 2][3],
                       qa[kc][0], qa[kc][1], qa[kc][2], qa[kc][3], b0, b1);
                MMA168(S[ng * 2 + 1][0], S[ng * 2 + 1][1], S[ng * 2 + 1][2], S[ng * 2 + 1][3],
                       qa[kc][0], qa[kc][1], qa[kc][2], qa[kc][3], b2, b3);
            }
        }

        if (kt == qt) {
            #pragma unroll
            for (int j = 0; j < 8; j++) {
                int col = kt * 64 + j * 8 + (lane & 3) * 2;
                if (col     > grow1) S[j][0] = -1e30f;
                if (col + 1 > grow1) S[j][1] = -1e30f;
                if (col     > grow2) S[j][2] = -1e30f;
                if (col + 1 > grow2) S[j][3] = -1e30f;
            }
        }

        float mx1 = -1e30f;
        float mx2 = -1e30f;
        #pragma unroll
        for (int j = 0; j < 8; j++) {
            mx1 = fmaxf(mx1, fmaxf(S[j][0], S[j][1]));
            mx2 = fmaxf(mx2, fmaxf(S[j][2], S[j][3]));
        }
        mx1 = fmaxf(mx1, __shfl_xor_sync(0xffffffffu, mx1, 1));
        mx1 = fmaxf(mx1, __shfl_xor_sync(0xffffffffu, mx1, 2));
        mx2 = fmaxf(mx2, __shfl_xor_sync(0xffffffffu, mx2, 1));
        mx2 = fmaxf(mx2, __shfl_xor_sync(0xffffffffu, mx2, 2));
        float mn1 = fmaxf(m1, mx1);
        float mn2 = fmaxf(m2, mx2);
        float al1 = __expf(m1 - mn1);
        float al2 = __expf(m2 - mn2);
        float sm1 = 0.0f;
        float sm2 = 0.0f;
        #pragma unroll
        for (int j = 0; j < 8; j++) {
            S[j][0] = __expf(S[j][0] - mn1);
            S[j][1] = __expf(S[j][1] - mn1);
            S[j][2] = __expf(S[j][2] - mn2);
            S[j][3] = __expf(S[j][3] - mn2);
            sm1 += S[j][0] + S[j][1];
            sm2 += S[j][2] + S[j][3];
        }
        sm1 += __shfl_xor_sync(0xffffffffu, sm1, 1);
        sm1 += __shfl_xor_sync(0xffffffffu, sm1, 2);
        sm2 += __shfl_xor_sync(0xffffffffu, sm2, 1);
        sm2 += __shfl_xor_sync(0xffffffffu, sm2, 2);
        l1 = l1 * al1 + sm1;
        l2 = l2 * al2 + sm2;
        m1 = mn1;
        m2 = mn2;
        #pragma unroll
        for (int j = 0; j < 8; j++) {
            O[j][0] *= al1; O[j][1] *= al1;
            O[j][2] *= al2; O[j][3] *= al2;
        }

        unsigned pa[4][4];
        #pragma unroll
        for (int kc = 0; kc < 4; kc++) {
            pa[kc][0] = pack_h2(S[2 * kc][0],     S[2 * kc][1]);
            pa[kc][1] = pack_h2(S[2 * kc][2],     S[2 * kc][3]);
            pa[kc][2] = pack_h2(S[2 * kc + 1][0], S[2 * kc + 1][1]);
            pa[kc][3] = pack_h2(S[2 * kc + 1][2], S[2 * kc + 1][3]);
        }

        #pragma unroll
        for (int dg = 0; dg < 4; dg++) {
            #pragma unroll
            for (int tc = 0; tc < 4; tc++) {
                int vrow = tc * 16 + ((lg & 1) << 3) + lr;
                int vch  = dg * 2 + (lg >> 1);
                unsigned v0, v1, v2, v3;
                LDSM4T(v0, v1, v2, v3, curV + vrow * 128 + ((vch ^ (vrow & 7)) << 4));
                MMA168(O[dg * 2][0], O[dg * 2][1], O[dg * 2][2], O[dg * 2][3],
                       pa[tc][0], pa[tc][1], pa[tc][2], pa[tc][3], v0, v1);
                MMA168(O[dg * 2 + 1][0], O[dg * 2 + 1][1], O[dg * 2 + 1][2], O[dg * 2 + 1][3],
                       pa[tc][0], pa[tc][1], pa[tc][2], pa[tc][3], v2, v3);
            }
        }

        if (kt < qt) {
            CPWAIT0();
            __syncthreads();
        }
    }

    float inv1 = 1.0f / l1;
    float inv2 = 1.0f / l2;
    size_t base1 = ((size_t)bb * SEQ + grow1) * 512 + hh * 64;
    size_t base2 = ((size_t)bb * SEQ + grow2) * 512 + hh * 64;
    #pragma unroll
    for (int j = 0; j < 8; j++) {
        int col = j * 8 + (lane & 3) * 2;
        *reinterpret_cast<__half2*>(&ctx[base1 + col]) =
            __floats2half2_rn(O[j][0] * inv1, O[j][1] * inv1);
        *reinterpret_cast<__half2*>(&ctx[base2 + col]) =
            __floats2half2_rn(O[j][2] * inv2, O[j][3] * inv2);
    }
}

extern "C" void kernel_launch(void* const* d_in, const int* in_sizes, int n_in,
                              void* d_out, int out_size)
{
    const float* src      = (const float*)d_in[0];
    const float* ln_w     = (const float*)d_in[1];
    const float* ln_b     = (const float*)d_in[2];
    const float* wqkv_w   = (const float*)d_in[3];
    const float* wqkv_b   = (const float*)d_in[4];
    const float* out_w    = (const float*)d_in[5];
    const float* out_b    = (const float*)d_in[6];
    const float* ffn_ln_w = (const float*)d_in[7];
    const float* ffn_ln_b = (const float*)d_in[8];
    const float* ff1_w    = (const float*)d_in[9];
    const float* ff1_b    = (const float*)d_in[10];
    const float* ff2_w    = (const float*)d_in[11];
    const float* ff2_b    = (const float*)d_in[12];
    float* out = (float*)d_out;

    __half *xln, *qkvh, *Q, *K, *V, *ctx, *hid, *wqkvh, *outwh, *ff1h, *ff2h;
    float *src2;
    float2* tab;
    cudaGetSymbolAddress((void**)&xln,   g_xln_h);
    cudaGetSymbolAddress((void**)&qkvh,  g_qkv_h);
    cudaGetSymbolAddress((void**)&Q,     g_Qh);
    cudaGetSymbolAddress((void**)&K,     g_Kh);
    cudaGetSymbolAddress((void**)&V,     g_Vh);
    cudaGetSymbolAddress((void**)&ctx,   g_ctx_h);
    cudaGetSymbolAddress((void**)&src2,  g_src2);
    cudaGetSymbolAddress((void**)&hid,   g_hid_h);
    cudaGetSymbolAddress((void**)&tab,   g_rope);
    cudaGetSymbolAddress((void**)&wqkvh, g_wqkv_h);
    cudaGetSymbolAddress((void**)&outwh, g_outw_h);
    cudaGetSymbolAddress((void**)&ff1h,  g_ff1_h);
    cudaGetSymbolAddress((void**)&ff2h,  g_ff2_h);

    int n4_total = N4_QKV + N4_OUT + N4_FF1 + N4_FF2;
    f2h_all<<<(n4_total + 255) / 256, 256>>>(wqkv_w, out_w, ff1_w, ff2_w,
                                             wqkvh, outwh, ff1h, ff2h);

    ln_kernel<<<ROWS, 128>>>(src, ln_w, ln_b, xln);
    gemm_cp<false, false, true><<<dim3(12, 64), 256>>>(xln, wqkvh, wqkv_b, nullptr,
                                                       nullptr, qkvh, ROWS, 3*D_MODEL, D_MODEL);
    rope_tab_kernel<<<(SEQ * 32) / 256, 256>>>(tab);
    rope_split_kernel<<<(ROWS * 8 * 32) / 256, 256>>>(qkvh, tab, Q, K, V);
    flash_mma<<<dim3(SEQ / 64, BH), 128>>>(Q, K, V, ctx);
    gemm_cp<false, true, false><<<dim3(4, 64), 256>>>(ctx, outwh, out_b, src,
                                                      src2, nullptr, ROWS, D_MODEL, D_MODEL);
    ln_kernel<<<ROWS, 128>>>(src2, ffn_ln_w, ffn_ln_b, xln);
    gemm_cp<true, false, true><<<dim3(16, 64), 256>>>(xln, ff1h, ff1_b, nullptr,
                                                      nullptr, hid, ROWS, D_FF, D_MODEL);
    gemm_cp<false, true, false><<<dim3(4, 64), 256>>>(hid, ff2h, ff2_b, src2,
                                                      out, nullptr, ROWS, D_MODEL, D_FF);
}

// round 8
// speedup vs baseline: 5.0957x; 1.0051x over previous
#include <cuda_runtime.h>
#include <cuda_fp16.h>
#include <mma.h>
#include <math.h>

using namespace nvcuda;

#define D_MODEL 512
#define N_HEADS 8
#define HEAD_DIM 64
#define D_FF 2048
#define SEQ 4096
#define BATCH 2
#define ROWS (BATCH*SEQ)
#define BH (BATCH*N_HEADS)

// scratch buffers (no allocation allowed)
__device__ __half  g_xln_h [ROWS*D_MODEL];
__device__ __half  g_Qh    [BH*SEQ*HEAD_DIM];
__device__ __half  g_Kh    [BH*SEQ*HEAD_DIM];
__device__ __half  g_Vh    [BH*SEQ*HEAD_DIM];
__device__ __half  g_ctx_h [ROWS*D_MODEL];
__device__ float   g_src2  [ROWS*D_MODEL];
__device__ __half  g_hid_h [ROWS*D_FF];
__device__ float2  g_rope  [SEQ*32];
__device__ __half  g_wqkv_h[3*D_MODEL*D_MODEL];
__device__ __half  g_outw_h[D_MODEL*D_MODEL];
__device__ __half  g_ff1_h [D_FF*D_MODEL];
__device__ __half  g_ff2_h [D_MODEL*D_FF];

// asm macros
#define CP16(dst, src) \
    asm volatile("cp.async.cg.shared.global [%0], [%1], 16;" :: "r"(dst), "l"(src))
#define CPCOMMIT() asm volatile("cp.async.commit_group;")
#define CPWAIT0()  asm volatile("cp.async.wait_group 0;")
#define CPWAIT1()  asm volatile("cp.async.wait_group 1;")
#define LDSM4(r0, r1, r2, r3, addr) \
    asm volatile("ldmatrix.sync.aligned.m8n8.x4.shared.b16 {%0,%1,%2,%3}, [%4];" \
                 : "=r"(r0), "=r"(r1), "=r"(r2), "=r"(r3) : "r"(addr))
#define LDSM4T(r0, r1, r2, r3, addr) \
    asm volatile("ldmatrix.sync.aligned.m8n8.x4.trans.shared.b16 {%0,%1,%2,%3}, [%4];" \
                 : "=r"(r0), "=r"(r1), "=r"(r2), "=r"(r3) : "r"(addr))
#define MMA168(c0, c1, c2, c3, a0, a1, a2, a3, b0, b1) \
    asm volatile("mma.sync.aligned.m16n8k16.row.col.f32.f16.f16.f32 " \
                 "{%0,%1,%2,%3},{%4,%5,%6,%7},{%8,%9},{%0,%1,%2,%3};" \
                 : "+f"(c0), "+f"(c1), "+f"(c2), "+f"(c3) \
                 : "r"(a0), "r"(a1), "r"(a2), "r"(a3), "r"(b0), "r"(b1))

__device__ __forceinline__ unsigned smem_u32(const void* p)
{
    return (unsigned)__cvta_generic_to_shared(p);
}
__device__ __forceinline__ unsigned pack_h2(float a, float b)
{
    __half2 h = __floats2half2_rn(a, b);
    return *reinterpret_cast<unsigned*>(&h);
}

// fused fp32 -> fp16 for all four weight tensors
#define N4_QKV (3*D_MODEL*D_MODEL/4)
#define N4_OUT (D_MODEL*D_MODEL/4)
#define N4_FF1 (D_FF*D_MODEL/4)
#define N4_FF2 (D_MODEL*D_FF/4)
__global__ void __launch_bounds__(256) f2h_all(const float* __restrict__ w0,
                                               const float* __restrict__ w1,
                                               const float* __restrict__ w2,
                                               const float* __restrict__ w3,
                                               __half* __restrict__ o0,
                                               __half* __restrict__ o1,
                                               __half* __restrict__ o2,
                                               __half* __restrict__ o3)
{
    int i = blockIdx.x * 256 + threadIdx.x;
    const float* in;
    __half* out;
    int k;
    if (i < N4_QKV) {
        in = w0; out = o0; k = i;
    } else if (i < N4_QKV + N4_OUT) {
        in = w1; out = o1; k = i - N4_QKV;
    } else if (i < N4_QKV + N4_OUT + N4_FF1) {
        in = w2; out = o2; k = i - N4_QKV - N4_OUT;
    } else if (i < N4_QKV + N4_OUT + N4_FF1 + N4_FF2) {
        in = w3; out = o3; k = i - N4_QKV - N4_OUT - N4_FF1;
    } else {
        return;
    }
    float4 v = reinterpret_cast<const float4*>(in)[k];
    reinterpret_cast<__half2*>(out)[k * 2 + 0] = __floats2half2_rn(v.x, v.y);
    reinterpret_cast<__half2*>(out)[k * 2 + 1] = __floats2half2_rn(v.z, v.w);
}

// LayerNorm, one block per row of 512, half output
__global__ void __launch_bounds__(128) ln_kernel(const float* __restrict__ x,
                                                 const float* __restrict__ w,
                                                 const float* __restrict__ b,
                                                 __half* __restrict__ y)
{
    int row = blockIdx.x;
    int t = threadIdx.x;
    const float4* xr = reinterpret_cast<const float4*>(x) + (size_t)row * 128;
    float4 v = xr[t];
    float s  = v.x + v.y + v.z + v.w;
    float ss = v.x*v.x + v.y*v.y + v.z*v.z + v.w*v.w;
    #pragma unroll
    for (int off = 16; off >= 1; off >>= 1) {
        s  += __shfl_xor_sync(0xffffffffu, s,  off);
        ss += __shfl_xor_sync(0xffffffffu, ss, off);
    }
    __shared__ float rs[4], rss[4];
    int wid = t >> 5;
    if ((t & 31) == 0) { rs[wid] = s; rss[wid] = ss; }
    __syncthreads();
    s  = rs[0] + rs[1] + rs[2] + rs[3];
    ss = rss[0] + rss[1] + rss[2] + rss[3];
    float mu  = s * (1.0f / 512.0f);
    float var = ss * (1.0f / 512.0f) - mu * mu;
    float r   = rsqrtf(var + 1e-5f);
    float4 w4 = reinterpret_cast<const float4*>(w)[t];
    float4 b4 = reinterpret_cast<const float4*>(b)[t];
    __half2* yr = reinterpret_cast<__half2*>(y) + (size_t)row * 256;
    yr[t * 2 + 0] = __floats2half2_rn((v.x - mu) * r * w4.x + b4.x,
                                      (v.y - mu) * r * w4.y + b4.y);
    yr[t * 2 + 1] = __floats2half2_rn((v.z - mu) * r * w4.z + b4.z,
                                      (v.w - mu) * r * w4.w + b4.w);
}

// RoPE table
__global__ void __launch_bounds__(256) rope_tab_kernel(float2* __restrict__ tab)
{
    int idx = blockIdx.x * 256 + threadIdx.x;
    int s = idx >> 5;
    int i = idx & 31;
    double freq = 1.0 / pow(10000.0, (double)i / 32.0);
    float ang = (float)((double)s * freq);
    tab[idx] = make_float2(cosf(ang), sinf(ang));
}

// fp16 wmma NT GEMM, 3-stage cp.async ring, one syncthreads per k-iter.
// OUTM: 0 = fp32 C (+resid), 1 = half Ch, 2 = fused rope split to Q/K/V
#define HLDA 40
#define STAGEH (128 * HLDA)
#define GEMM_SMEM (3 * STAGEH * 2 * 2)

template<bool RELU, bool RESID, int OUTM>
__global__ void __launch_bounds__(256) gemm3(const __half* __restrict__ A,
                                             const __half* __restrict__ W,
                                             const float* __restrict__ bias,
                                             const float* __restrict__ resid,
                                             float* __restrict__ C,
                                             __half* __restrict__ Ch,
                                             __half* __restrict__ Qp,
                                             __half* __restrict__ Kp,
                                             __half* __restrict__ Vp,
                                             const float2* __restrict__ tab,
                                             int M, int N, int K)
{
    extern __shared__ __half sm3[];
    __half* Asb = sm3;
    __half* Wsb = sm3 + 3 * STAGEH;
    int tid = threadIdx.x;
    int wid = tid >> 5;
    int lane = tid & 31;
    int wr = wid >> 1;
    int wc = wid & 1;
    int bm = blockIdx.y * 128;
    int bn = blockIdx.x * 128;
    int nK = K >> 5;

    // per-thread load slots: 2 chunks of A + 2 chunks of W per stage
    int ldrow0 = tid >> 2;
    int ldc0   = tid & 3;
    int ldrow1 = (tid + 256) >> 2;
    int ldc1   = (tid + 256) & 3;
    const __half* gA0 = A + (size_t)(bm + ldrow0) * K + ldc0 * 8;
    const __half* gA1 = A + (size_t)(bm + ldrow1) * K + ldc1 * 8;
    const __half* gW0 = W + (size_t)(bn + ldrow0) * K + ldc0 * 8;
    const __half* gW1 = W + (size_t)(bn + ldrow1) * K + ldc1 * 8;
    unsigned offA0 = (unsigned)((ldrow0 * HLDA + ldc0 * 8) * 2);
    unsigned offA1 = (unsigned)((ldrow1 * HLDA + ldc1 * 8) * 2);
    unsigned aAs = smem_u32(Asb);
    unsigned aWs = smem_u32(Wsb);

    wmma::fragment<wmma::accumulator, 16, 16, 16, float> acc[2][4];
    #pragma unroll
    for (int i = 0; i < 2; i++) {
        #pragma unroll
        for (int j = 0; j < 4; j++) {
            wmma::fill_fragment(acc[i][j], 0.0f);
        }
    }

    // prologue: stages 0 and 1
    CP16(aAs + offA0, gA0);
    CP16(aAs + offA1, gA1);
    CP16(aWs + offA0, gW0);
    CP16(aWs + offA1, gW1);
    CPCOMMIT();
    CP16(aAs + STAGEH * 2 + offA0, gA0 + 32);
    CP16(aAs + STAGEH * 2 + offA1, gA1 + 32);
    CP16(aWs + STAGEH * 2 + offA0, gW0 + 32);
    CP16(aWs + STAGEH * 2 + offA1, gW1 + 32);
    CPCOMMIT();

    for (int kt = 0; kt < nK; kt++) {
        if (kt < nK - 1) {
            CPWAIT1();
        } else {
            CPWAIT0();
        }
        __syncthreads();
        if (kt + 2 < nK) {
            int stn = (kt + 2) % 3;
            unsigned sb = (unsigned)(stn * STAGEH * 2);
            int koff = (kt + 2) * 32;
            CP16(aAs + sb + offA0, gA0 + koff);
            CP16(aAs + sb + offA1, gA1 + koff);
            CP16(aWs + sb + offA0, gW0 + koff);
            CP16(aWs + sb + offA1, gW1 + koff);
            CPCOMMIT();
        }
        const __half* Asc = Asb + (kt % 3) * STAGEH;
        const __half* Wsc = Wsb + (kt % 3) * STAGEH;
        #pragma unroll
        for (int ks = 0; ks < 2; ks++) {
            int k16 = ks * 16;
            wmma::fragment<wmma::matrix_a, 16, 16, 16, __half, wmma::row_major> af[2];
            #pragma unroll
            for (int i = 0; i < 2; i++) {
                wmma::load_matrix_sync(af[i], &Asc[(wr * 32 + i * 16) * HLDA + k16], HLDA);
            }
            wmma::fragment<wmma::matrix_b, 16, 16, 16, __half, wmma::col_major> bf[4];
            #pragma unroll
            for (int j = 0; j < 4; j++) {
                wmma::load_matrix_sync(bf[j], &Wsc[(wc * 64 + j * 16) * HLDA + k16], HLDA);
            }
            #pragma unroll
            for (int i = 0; i < 2; i++) {
                #pragma unroll
                for (int j = 0; j < 4; j++) {
                    wmma::mma_sync(acc[i][j], af[i], bf[j], acc[i][j]);
                }
            }
        }
    }
    __syncthreads();

    float* cbuf = reinterpret_cast<float*>(Asb) + wid * 16 * 20;
    #pragma unroll
    for (int i = 0; i < 2; i++) {
        #pragma unroll
        for (int j = 0; j < 4; j++) {
            wmma::store_matrix_sync(cbuf, acc[i][j], 20, wmma::mem_row_major);
            __syncwarp();
            #pragma unroll
            for (int u = 0; u < 2; u++) {
                int e = lane + u * 32;
                int row = e >> 2;
                int c4 = (e & 3) * 4;
                float4 o = *reinterpret_cast<float4*>(&cbuf[row * 20 + c4]);
                int gr = bm + wr * 32 + i * 16 + row;
                int gc = bn + wc * 64 + j * 16 + c4;
                float4 bb = *reinterpret_cast<const float4*>(&bias[gc]);
                o.x += bb.x; o.y += bb.y; o.z += bb.z; o.w += bb.w;
                if (RELU) {
                    o.x = fmaxf(o.x, 0.0f); o.y = fmaxf(o.y, 0.0f);
                    o.z = fmaxf(o.z, 0.0f); o.w = fmaxf(o.w, 0.0f);
                }
                if (RESID) {
                    float4 rv = *reinterpret_cast<const float4*>(&resid[(size_t)gr * N + gc]);
                    o.x += rv.x; o.y += rv.y; o.z += rv.z; o.w += rv.w;
                }
                if (OUTM == 0) {
                    *reinterpret_cast<float4*>(&C[(size_t)gr * N + gc]) = o;
                } else if (OUTM == 1) {
                    *reinterpret_cast<__half2*>(&Ch[(size_t)gr * N + gc]) =
                        __floats2half2_rn(o.x, o.y);
                    *reinterpret_cast<__half2*>(&Ch[(size_t)gr * N + gc + 2]) =
                        __floats2half2_rn(o.z, o.w);
                } else {
                    // fused rope + split: gc in [0, 1536)
                    int type = gc >> 9;
                    int head = (gc >> 6) & 7;
                    int d    = gc & 63;
                    int s    = gr & (SEQ - 1);
                    int bi   = gr >> 12;
                    size_t oo = ((((size_t)bi * 8 + head) * SEQ) + s) * 64 + d;
                    if (type == 2) {
                        *reinterpret_cast<__half2*>(&Vp[oo]) = __floats2half2_rn(o.x, o.y);
                        *reinterpret_cast<__half2*>(&Vp[oo + 2]) = __floats2half2_rn(o.z, o.w);
                    } else {
                        float2 cs0 = tab[s * 32 + (d >> 1)];
                        float2 cs1 = tab[s * 32 + (d >> 1) + 1];
                        float r0 = o.x * cs0.x - o.y * cs0.y;
                        float r1 = o.x * cs0.y + o.y * cs0.x;
                        float r2 = o.z * cs1.x - o.w * cs1.y;
                        float r3 = o.z * cs1.y + o.w * cs1.x;
                        if (type == 0) {
                            *reinterpret_cast<__half2*>(&Qp[oo]) =
                                __floats2half2_rn(r0 * 0.125f, r1 * 0.125f);
                            *reinterpret_cast<__half2*>(&Qp[oo + 2]) =
                                __floats2half2_rn(r2 * 0.125f, r3 * 0.125f);
                        } else {
                            *reinterpret_cast<__half2*>(&Kp[oo]) = __floats2half2_rn(r0, r1);
                            *reinterpret_cast<__half2*>(&Kp[oo + 2]) = __floats2half2_rn(r2, r3);
                        }
                    }
                }
            }
            __syncwarp();
        }
    }
}

// register-resident causal flash attention (identical to round-6/7 passing version)
__global__ void __launch_bounds__(128) flash_mma(const __half* __restrict__ Qg,
                                                 const __half* __restrict__ Kg,
                                                 const __half* __restrict__ Vg,
                                                 __half* __restrict__ ctx)
{
    __shared__ __half sQ[4096];
    __shared__ __half sK0[4096];
    __shared__ __half sK1[4096];
    __shared__ __half sV0[4096];
    __shared__ __half sV1[4096];

    int qt = (int)gridDim.x - 1 - blockIdx.x;
    int bh = blockIdx.y;
    int bb = bh >> 3;
    int hh = bh & 7;
    const __half* Qb = Qg + ((size_t)bh * SEQ + qt * 64) * 64;
    const __half* Kb = Kg + (size_t)bh * SEQ * 64;
    const __half* Vb = Vg + (size_t)bh * SEQ * 64;

    int tid = threadIdx.x;
    int lane = tid & 31;
    int wq = tid >> 5;
    int lr = lane & 7;
    int lg = lane >> 3;
    unsigned aQ = smem_u32(sQ);
    unsigned aK0 = smem_u32(sK0);
    unsigned aK1 = smem_u32(sK1);
    unsigned aV0 = smem_u32(sV0);
    unsigned aV1 = smem_u32(sV1);

    {
        int r = tid >> 1;
        int cbase = (tid & 1) * 4;
        #pragma unroll
        for (int c = cbase; c < cbase + 4; c++) {
            CP16(aQ  + r * 128 + ((c ^ (r & 7)) << 4), Qb + r * 64 + c * 8);
            CP16(aK0 + r * 128 + ((c ^ (r & 7)) << 4), Kb + r * 64 + c * 8);
            CP16(aV0 + r * 128 + ((c ^ (r & 7)) << 4), Vb + r * 64 + c * 8);
        }
    }
    CPCOMMIT();
    CPWAIT0();
    __syncthreads();

    unsigned qa[4][4];
    #pragma unroll
    for (int kc = 0; kc < 4; kc++) {
        int qrow = wq * 16 + ((lg & 1) << 3) + lr;
        int qch  = kc * 2 + (lg >> 1);
        LDSM4(qa[kc][0], qa[kc][1], qa[kc][2], qa[kc][3],
              aQ + qrow * 128 + ((qch ^ (qrow & 7)) << 4));
    }

    float O[8][4];
    #pragma unroll
    for (int j = 0; j < 8; j++) {
        O[j][0] = 0.0f; O[j][1] = 0.0f; O[j][2] = 0.0f; O[j][3] = 0.0f;
    }
    float m1 = -1e30f;
    float m2 = -1e30f;
    float l1 = 0.0f;
    float l2 = 0.0f;

    int grow1 = qt * 64 + wq * 16 + (lane >> 2);
    int grow2 = grow1 + 8;

    for (int kt = 0; kt <= qt; ++kt) {
        unsigned curK = (kt & 1) ? aK1 : aK0;
        unsigned curV = (kt & 1) ? aV1 : aV0;
        unsigned nxtK = (kt & 1) ? aK0 : aK1;
        unsigned nxtV = (kt & 1) ? aV0 : aV1;
        if (kt < qt) {
            const __half* Kn = Kb + (size_t)(kt + 1) * 4096;
            const __half* Vn = Vb + (size_t)(kt + 1) * 4096;
            int r = tid >> 1;
            int cbase = (tid & 1) * 4;
            #pragma unroll
            for (int c = cbase; c < cbase + 4; c++) {
                CP16(nxtK + r * 128 + ((c ^ (r & 7)) << 4), Kn + r * 64 + c * 8);
                CP16(nxtV + r * 128 + ((c ^ (r & 7)) << 4), Vn + r * 64 + c * 8);
            }
            CPCOMMIT();
        }

        float S[8][4];
        #pragma unroll
        for (int j = 0; j < 8; j++) {
            S[j][0] = 0.0f; S[j][1] = 0.0f; S[j][2] = 0.0f; S[j][3] = 0.0f;
        }
        #pragma unroll
        for (int ng = 0; ng < 4; ng++) {
            #pragma unroll
            for (int kc = 0; kc < 4; kc++) {
                int krow = ng * 16 + ((lg >> 1) << 3) + lr;
                int kch  = kc * 2 + (lg & 1);
                unsigned b0, b1, b2, b3;
                LDSM4(b0, b1, b2, b3, curK + krow * 128 + ((kch ^ (krow & 7)) << 4));
                MMA168(S[ng * 2][0], S[ng * 2][1], S[ng * 2][2], S[ng * 2][3],
                       qa[kc][0], qa[kc][1], qa[kc][2], qa[kc][3], b0, b1);
                MMA168(S[ng * 2 + 1][0], S[ng * 2 + 1][1], S[ng * 2 + 1][2], S[ng * 2 + 1][3],
                       qa[kc][0], qa[kc][1], qa[kc][2], qa[kc][3], b2, b3);
            }
        }

        if (kt == qt) {
            #pragma unroll
            for (int j = 0; j < 8; j++) {
                int col = kt * 64 + j * 8 + (lane & 3) * 2;
                if (col     > grow1) S[j][0] = -1e30f;
                if (col + 1 > grow1) S[j][1] = -1e30f;
                if (col     > grow2) S[j][2] = -1e30f;
                if (col + 1 > grow2) S[j][3] = -1e30f;
            }
        }

        float mx1 = -1e30f;
        float mx2 = -1e30f;
        #pragma unroll
        for (int j = 0; j < 8; j++) {
            mx1 = fmaxf(mx1, fmaxf(S[j][0], S[j][1]));
            mx2 = fmaxf(mx2, fmaxf(S[j][2], S[j][3]));
        }
        mx1 = fmaxf(mx1, __shfl_xor_sync(0xffffffffu, mx1, 1));
        mx1 = fmaxf(mx1, __shfl_xor_sync(0xffffffffu, mx1, 2));
        mx2 = fmaxf(mx2, __shfl_xor_sync(0xffffffffu, mx2, 1));
        mx2 = fmaxf(mx2, __shfl_xor_sync(0xffffffffu, mx2, 2));
        float mn1 = fmaxf(m1, mx1);
        float mn2 = fmaxf(m2, mx2);
        float al1 = __expf(m1 - mn1);
        float al2 = __expf(m2 - mn2);
        float sm1 = 0.0f;
        float sm2 = 0.0f;
        #pragma unroll
        for (int j = 0; j < 8; j++) {
            S[j][0] = __expf(S[j][0] - mn1);
            S[j][1] = __expf(S[j][1] - mn1);
            S[j][2] = __expf(S[j][2] - mn2);
            S[j][3] = __expf(S[j][3] - mn2);
            sm1 += S[j][0] + S[j][1];
            sm2 += S[j][2] + S[j][3];
        }
        sm1 += __shfl_xor_sync(0xffffffffu, sm1, 1);
        sm1 += __shfl_xor_sync(0xffffffffu, sm1, 2);
        sm2 += __shfl_xor_sync(0xffffffffu, sm2, 1);
        sm2 += __shfl_xor_sync(0xffffffffu, sm2, 2);
        l1 = l1 * al1 + sm1;
        l2 = l2 * al2 + sm2;
        m1 = mn1;
        m2 = mn2;
        #pragma unroll
        for (int j = 0; j < 8; j++) {
            O[j][0] *= al1; O[j][1] *= al1;
            O[j][2] *= al2; O[j][3] *= al2;
        }

        unsigned pa[4][4];
        #pragma unroll
        for (int kc = 0; kc < 4; kc++) {
            pa[kc][0] = pack_h2(S[2 * kc][0],     S[2 * kc][1]);
            pa[kc][1] = pack_h2(S[2 * kc][2],     S[2 * kc][3]);
            pa[kc][2] = pack_h2(S[2 * kc + 1][0], S[2 * kc + 1][1]);
            pa[kc][3] = pack_h2(S[2 * kc + 1][2], S[2 * kc + 1][3]);
        }

        #pragma unroll
        for (int dg = 0; dg < 4; dg++) {
            #pragma unroll
            for (int tc = 0; tc < 4; tc++) {
                int vrow = tc * 16 + ((lg & 1) << 3) + lr;
                int vch  = dg * 2 + (lg >> 1);
                unsigned v0, v1, v2, v3;
                LDSM4T(v0, v1, v2, v3, curV + vrow * 128 + ((vch ^ (vrow & 7)) << 4));
                MMA168(O[dg * 2][0], O[dg * 2][1], O[dg * 2][2], O[dg * 2][3],
                       pa[tc][0], pa[tc][1], pa[tc][2], pa[tc][3], v0, v1);
                MMA168(O[dg * 2 + 1][0], O[dg * 2 + 1][1], O[dg * 2 + 1][2], O[dg * 2 + 1][3],
                       pa[tc][0], pa[tc][1], pa[tc][2], pa[tc][3], v2, v3);
            }
        }

        if (kt < qt) {
            CPWAIT0();
            __syncthreads();
        }
    }

    float inv1 = 1.0f / l1;
    float inv2 = 1.0f / l2;
    size_t base1 = ((size_t)bb * SEQ + grow1) * 512 + hh * 64;
    size_t base2 = ((size_t)bb * SEQ + grow2) * 512 + hh * 64;
    #pragma unroll
    for (int j = 0; j < 8; j++) {
        int col = j * 8 + (lane & 3) * 2;
        *reinterpret_cast<__half2*>(&ctx[base1 + col]) =
            __floats2half2_rn(O[j][0] * inv1, O[j][1] * inv1);
        *reinterpret_cast<__half2*>(&ctx[base2 + col]) =
            __floats2half2_rn(O[j][2] * inv2, O[j][3] * inv2);
    }
}

extern "C" void kernel_launch(void* const* d_in, const int* in_sizes, int n_in,
                              void* d_out, int out_size)
{
    const float* src      = (const float*)d_in[0];
    const float* ln_w     = (const float*)d_in[1];
    const float* ln_b     = (const float*)d_in[2];
    const float* wqkv_w   = (const float*)d_in[3];
    const float* wqkv_b   = (const float*)d_in[4];
    const float* out_w    = (const float*)d_in[5];
    const float* out_b    = (const float*)d_in[6];
    const float* ffn_ln_w = (const float*)d_in[7];
    const float* ffn_ln_b = (const float*)d_in[8];
    const float* ff1_w    = (const float*)d_in[9];
    const float* ff1_b    = (const float*)d_in[10];
    const float* ff2_w    = (const float*)d_in[11];
    const float* ff2_b    = (const float*)d_in[12];
    float* out = (float*)d_out;

    __half *xln, *Q, *K, *V, *ctx, *hid, *wqkvh, *outwh, *ff1h, *ff2h;
    float *src2;
    float2* tab;
    cudaGetSymbolAddress((void**)&xln,   g_xln_h);
    cudaGetSymbolAddress((void**)&Q,     g_Qh);
    cudaGetSymbolAddress((void**)&K,     g_Kh);
    cudaGetSymbolAddress((void**)&V,     g_Vh);
    cudaGetSymbolAddress((void**)&ctx,   g_ctx_h);
    cudaGetSymbolAddress((void**)&src2,  g_src2);
    cudaGetSymbolAddress((void**)&hid,   g_hid_h);
    cudaGetSymbolAddress((void**)&tab,   g_rope);
    cudaGetSymbolAddress((void**)&wqkvh, g_wqkv_h);
    cudaGetSymbolAddress((void**)&outwh, g_outw_h);
    cudaGetSymbolAddress((void**)&ff1h,  g_ff1_h);
    cudaGetSymbolAddress((void**)&ff2h,  g_ff2_h);

    cudaFuncSetAttribute(gemm3<false, false, 2>,
                         cudaFuncAttributeMaxDynamicSharedMemorySize, GEMM_SMEM);
    cudaFuncSetAttribute(gemm3<false, true, 0>,
                         cudaFuncAttributeMaxDynamicSharedMemorySize, GEMM_SMEM);
    cudaFuncSetAttribute(gemm3<true, false, 1>,
                         cudaFuncAttributeMaxDynamicSharedMemorySize, GEMM_SMEM);

    int n4_total = N4_QKV + N4_OUT + N4_FF1 + N4_FF2;
    f2h_all<<<(n4_total + 255) / 256, 256>>>(wqkv_w, out_w, ff1_w, ff2_w,
                                             wqkvh, outwh, ff1h, ff2h);
    rope_tab_kernel<<<(SEQ * 32) / 256, 256>>>(tab);
    ln_kernel<<<ROWS, 128>>>(src, ln_w, ln_b, xln);

    // QKV projection with fused rope + split
    gemm3<false, false, 2><<<dim3(12, 64), 256, GEMM_SMEM>>>(
        xln, wqkvh, wqkv_b, nullptr, nullptr, nullptr, Q, K, V, tab,
        ROWS, 3 * D_MODEL, D_MODEL);

    flash_mma<<<dim3(SEQ / 64, BH), 128>>>(Q, K, V, ctx);

    gemm3<false, true, 0><<<dim3(4, 64), 256, GEMM_SMEM>>>(
        ctx, outwh, out_b, src, src2, nullptr, nullptr, nullptr, nullptr, nullptr,
        ROWS, D_MODEL, D_MODEL);

    ln_kernel<<<ROWS, 128>>>(src2, ffn_ln_w, ffn_ln_b, xln);

    gemm3<true, false, 1><<<dim3(16, 64), 256, GEMM_SMEM>>>(
        xln, ff1h, ff1_b, nullptr, nullptr, hid, nullptr, nullptr, nullptr, nullptr,
        ROWS, D_FF, D_MODEL);

    gemm3<false, true, 0><<<dim3(4, 64), 256, GEMM_SMEM>>>(
        hid, ff2h, ff2_b, src2, out, nullptr, nullptr, nullptr, nullptr, nullptr,
        ROWS, D_MODEL, D_FF);
}

// round 10
// speedup vs baseline: 5.7531x; 1.1290x over previous
#include <cuda_runtime.h>
#include <cuda_fp16.h>
#include <math.h>

#define D_MODEL 512
#define N_HEADS 8
#define HEAD_DIM 64
#define D_FF 2048
#define SEQ 4096
#define BATCH 2
#define ROWS (BATCH*SEQ)
#define BH (BATCH*N_HEADS)

// scratch buffers (no allocation allowed)
__device__ __half  g_xln_h [ROWS*D_MODEL];
__device__ __half  g_Qh    [BH*SEQ*HEAD_DIM];
__device__ __half  g_Kh    [BH*SEQ*HEAD_DIM];
__device__ __half  g_Vh    [BH*SEQ*HEAD_DIM];
__device__ __half  g_ctx_h [ROWS*D_MODEL];
__device__ float   g_src2  [ROWS*D_MODEL];
__device__ __half  g_hid_h [ROWS*D_FF];
__device__ float2  g_rope  [SEQ*32];
__device__ __half  g_wqkv_h[3*D_MODEL*D_MODEL];
__device__ __half  g_outw_h[D_MODEL*D_MODEL];
__device__ __half  g_ff1_h [D_FF*D_MODEL];
__device__ __half  g_ff2_h [D_MODEL*D_FF];

// asm macros
#define CP16(dst, src) \
    asm volatile("cp.async.cg.shared.global [%0], [%1], 16;" :: "r"(dst), "l"(src))
#define CPCOMMIT() asm volatile("cp.async.commit_group;")
#define CPWAIT0()  asm volatile("cp.async.wait_group 0;")
#define CPWAIT1()  asm volatile("cp.async.wait_group 1;")
#define LDSM4(r0, r1, r2, r3, addr) \
    asm volatile("ldmatrix.sync.aligned.m8n8.x4.shared.b16 {%0,%1,%2,%3}, [%4];" \
                 : "=r"(r0), "=r"(r1), "=r"(r2), "=r"(r3) : "r"(addr))
#define LDSM4T(r0, r1, r2, r3, addr) \
    asm volatile("ldmatrix.sync.aligned.m8n8.x4.trans.shared.b16 {%0,%1,%2,%3}, [%4];" \
                 : "=r"(r0), "=r"(r1), "=r"(r2), "=r"(r3) : "r"(addr))
#define MMA168(c0, c1, c2, c3, a0, a1, a2, a3, b0, b1) \
    asm volatile("mma.sync.aligned.m16n8k16.row.col.f32.f16.f16.f32 " \
                 "{%0,%1,%2,%3},{%4,%5,%6,%7},{%8,%9},{%0,%1,%2,%3};" \
                 : "+f"(c0), "+f"(c1), "+f"(c2), "+f"(c3) \
                 : "r"(a0), "r"(a1), "r"(a2), "r"(a3), "r"(b0), "r"(b1))

__device__ __forceinline__ unsigned smem_u32(const void* p)
{
    return (unsigned)__cvta_generic_to_shared(p);
}
__device__ __forceinline__ unsigned pack_h2(float a, float b)
{
    __half2 h = __floats2half2_rn(a, b);
    return *reinterpret_cast<unsigned*>(&h);
}

// fused fp32 -> fp16 for all four weight tensors
#define N4_QKV (3*D_MODEL*D_MODEL/4)
#define N4_OUT (D_MODEL*D_MODEL/4)
#define N4_FF1 (D_FF*D_MODEL/4)
#define N4_FF2 (D_MODEL*D_FF/4)
__global__ void __launch_bounds__(256) f2h_all(const float* __restrict__ w0,
                                               const float* __restrict__ w1,
                                               const float* __restrict__ w2,
                                               const float* __restrict__ w3,
                                               __half* __restrict__ o0,
                                               __half* __restrict__ o1,
                                               __half* __restrict__ o2,
                                               __half* __restrict__ o3)
{
    int i = blockIdx.x * 256 + threadIdx.x;
    const float* in;
    __half* out;
    int k;
    if (i < N4_QKV) {
        in = w0; out = o0; k = i;
    } else if (i < N4_QKV + N4_OUT) {
        in = w1; out = o1; k = i - N4_QKV;
    } else if (i < N4_QKV + N4_OUT + N4_FF1) {
        in = w2; out = o2; k = i - N4_QKV - N4_OUT;
    } else if (i < N4_QKV + N4_OUT + N4_FF1 + N4_FF2) {
        in = w3; out = o3; k = i - N4_QKV - N4_OUT - N4_FF1;
    } else {
        return;
    }
    float4 v = reinterpret_cast<const float4*>(in)[k];
    reinterpret_cast<__half2*>(out)[k * 2 + 0] = __floats2half2_rn(v.x, v.y);
    reinterpret_cast<__half2*>(out)[k * 2 + 1] = __floats2half2_rn(v.z, v.w);
}

// LayerNorm, one block per row of 512, half output
__global__ void __launch_bounds__(128) ln_kernel(const float* __restrict__ x,
                                                 const float* __restrict__ w,
                                                 const float* __restrict__ b,
                                                 __half* __restrict__ y)
{
    int row = blockIdx.x;
    int t = threadIdx.x;
    const float4* xr = reinterpret_cast<const float4*>(x) + (size_t)row * 128;
    float4 v = xr[t];
    float s  = v.x + v.y + v.z + v.w;
    float ss = v.x*v.x + v.y*v.y + v.z*v.z + v.w*v.w;
    #pragma unroll
    for (int off = 16; off >= 1; off >>= 1) {
        s  += __shfl_xor_sync(0xffffffffu, s,  off);
        ss += __shfl_xor_sync(0xffffffffu, ss, off);
    }
    __shared__ float rs[4], rss[4];
    int wid = t >> 5;
    if ((t & 31) == 0) { rs[wid] = s; rss[wid] = ss; }
    __syncthreads();
    s  = rs[0] + rs[1] + rs[2] + rs[3];
    ss = rss[0] + rss[1] + rss[2] + rss[3];
    float mu  = s * (1.0f / 512.0f);
    float var = ss * (1.0f / 512.0f) - mu * mu;
    float r   = rsqrtf(var + 1e-5f);
    float4 w4 = reinterpret_cast<const float4*>(w)[t];
    float4 b4 = reinterpret_cast<const float4*>(b)[t];
    __half2* yr = reinterpret_cast<__half2*>(y) + (size_t)row * 256;
    yr[t * 2 + 0] = __floats2half2_rn((v.x - mu) * r * w4.x + b4.x,
                                      (v.y - mu) * r * w4.y + b4.y);
    yr[t * 2 + 1] = __floats2half2_rn((v.z - mu) * r * w4.z + b4.z,
                                      (v.w - mu) * r * w4.w + b4.w);
}

// RoPE table
__global__ void __launch_bounds__(256) rope_tab_kernel(float2* __restrict__ tab)
{
    int idx = blockIdx.x * 256 + threadIdx.x;
    int s = idx >> 5;
    int i = idx & 31;
    double freq = 1.0 / pow(10000.0, (double)i / 32.0);
    float ang = (float)((double)s * freq);
    tab[idx] = make_float2(cosf(ang), sinf(ang));
}

// raw mma NT GEMM: C[M,N] = A[M,K] * W[N,K]^T
// 128x128 block tile, BK=64, 3-stage cp.async ring, ldmatrix + XOR swizzle.
// 8 warps in 4x2, warp tile 32x64, register accumulators, direct epilogue.
// OUTM: 0 = fp32 C (+resid), 1 = half Ch, 2 = fused rope split to Q/K/V
#define GSTAGE 16384u
#define GEMM_SMEM (6 * 16384)

template<bool RELU, bool RESID, int OUTM>
__global__ void __launch_bounds__(256) gemm_mma(const __half* __restrict__ A,
                                                const __half* __restrict__ W,
                                                const float* __restrict__ bias,
                                                const float* __restrict__ resid,
                                                float* __restrict__ C,
                                                __half* __restrict__ Ch,
                                                __half* __restrict__ Qp,
                                                __half* __restrict__ Kp,
                                                __half* __restrict__ Vp,
                                                const float2* __restrict__ tab,
                                                int M, int N, int K)
{
    extern __shared__ __half smg[];
    unsigned aA = smem_u32(smg);
    unsigned aB = aA + 3 * GSTAGE;
    int tid = threadIdx.x;
    int lane = tid & 31;
    int wid = tid >> 5;
    int wr = wid >> 1;
    int wc = wid & 1;
    int lr = lane & 7;
    int lg = lane >> 3;
    int bm = blockIdx.y * 128;
    int bn = blockIdx.x * 128;
    int nK = K >> 6;

    const __half* Ag = A + (size_t)bm * K;
    const __half* Wg = W + (size_t)bn * K;

    float acc[2][8][4];
    #pragma unroll
    for (int i = 0; i < 2; i++) {
        #pragma unroll
        for (int j = 0; j < 8; j++) {
            acc[i][j][0] = 0.0f; acc[i][j][1] = 0.0f;
            acc[i][j][2] = 0.0f; acc[i][j][3] = 0.0f;
        }
    }

    // prologue: stages 0 and 1
    for (int st = 0; st < 2; st++) {
        unsigned dA = aA + (unsigned)st * GSTAGE;
        unsigned dB = aB + (unsigned)st * GSTAGE;
        int k0 = st * 64;
        #pragma unroll
        for (int i2 = 0; i2 < 4; i2++) {
            int idx = tid + i2 * 256;
            int rr = idx >> 3;
            int cc = idx & 7;
            CP16(dA + rr * 128 + ((cc ^ (rr & 7)) << 4), Ag + (size_t)rr * K + k0 + cc * 8);
            CP16(dB + rr * 128 + ((cc ^ (rr & 7)) << 4), Wg + (size_t)rr * K + k0 + cc * 8);
        }
        CPCOMMIT();
    }

    for (int kt = 0; kt < nK; kt++) {
        if (kt < nK - 1) {
            CPWAIT1();
        } else {
            CPWAIT0();
        }
        __syncthreads();
        if (kt + 2 < nK) {
            int st = (kt + 2) % 3;
            unsigned dA = aA + (unsigned)st * GSTAGE;
            unsigned dB = aB + (unsigned)st * GSTAGE;
            int k0 = (kt + 2) * 64;
            #pragma unroll
            for (int i2 = 0; i2 < 4; i2++) {
                int idx = tid + i2 * 256;
                int rr = idx >> 3;
                int cc = idx & 7;
                CP16(dA + rr * 128 + ((cc ^ (rr & 7)) << 4), Ag + (size_t)rr * K + k0 + cc * 8);
                CP16(dB + rr * 128 + ((cc ^ (rr & 7)) << 4), Wg + (size_t)rr * K + k0 + cc * 8);
            }
            CPCOMMIT();
        }
        unsigned cA = aA + (unsigned)(kt % 3) * GSTAGE;
        unsigned cB = aB + (unsigned)(kt % 3) * GSTAGE;
        #pragma unroll
        for (int kc = 0; kc < 4; kc++) {
            unsigned af0[4], af1[4];
            int arow = wr * 32 + ((lg & 1) << 3) + lr;
            int ach = kc * 2 + (lg >> 1);
            LDSM4(af0[0], af0[1], af0[2], af0[3],
                  cA + arow * 128 + ((ach ^ (arow & 7)) << 4));
            int arow2 = arow + 16;
            LDSM4(af1[0], af1[1], af1[2], af1[3],
                  cA + arow2 * 128 + ((ach ^ (arow2 & 7)) << 4));
            #pragma unroll
            for (int jj = 0; jj < 4; jj++) {
                int brow = wc * 64 + jj * 16 + ((lg >> 1) << 3) + lr;
                int bch = kc * 2 + (lg & 1);
                unsigned b0, b1, b2, b3;
                LDSM4(b0, b1, b2, b3, cB + brow * 128 + ((bch ^ (brow & 7)) << 4));
                MMA168(acc[0][2*jj][0], acc[0][2*jj][1], acc[0][2*jj][2], acc[0][2*jj][3],
                       af0[0], af0[1], af0[2], af0[3], b0, b1);
                MMA168(acc[0][2*jj+1][0], acc[0][2*jj+1][1], acc[0][2*jj+1][2], acc[0][2*jj+1][3],
                       af0[0], af0[1], af0[2], af0[3], b2, b3);
                MMA168(acc[1][2*jj][0], acc[1][2*jj][1], acc[1][2*jj][2], acc[1][2*jj][3],
                       af1[0], af1[1], af1[2], af1[3], b0, b1);
                MMA168(acc[1][2*jj+1][0], acc[1][2*jj+1][1], acc[1][2*jj+1][2], acc[1][2*jj+1][3],
                       af1[0], af1[1], af1[2], af1[3], b2, b3);
            }
        }
    }

    // epilogue straight from registers
    #pragma unroll
    for (int i = 0; i < 2; i++) {
        int r1 = bm + wr * 32 + i * 16 + (lane >> 2);
        int r2 = r1 + 8;
        #pragma unroll
        for (int j = 0; j < 8; j++) {
            int gc = bn + wc * 64 + j * 8 + (lane & 3) * 2;
            float2 bb = *reinterpret_cast<const float2*>(&bias[gc]);
            float c0 = acc[i][j][0] + bb.x;
            float c1 = acc[i][j][1] + bb.y;
            float c2 = acc[i][j][2] + bb.x;
            float c3 = acc[i][j][3] + bb.y;
            if (RELU) {
                c0 = fmaxf(c0, 0.0f); c1 = fmaxf(c1, 0.0f);
                c2 = fmaxf(c2, 0.0f); c3 = fmaxf(c3, 0.0f);
            }
            if (OUTM == 0) {
                if (RESID) {
                    float2 rv1 = *reinterpret_cast<const float2*>(&resid[(size_t)r1 * N + gc]);
                    float2 rv2 = *reinterpret_cast<const float2*>(&resid[(size_t)r2 * N + gc]);
                    c0 += rv1.x; c1 += rv1.y;
                    c2 += rv2.x; c3 += rv2.y;
                }
                *reinterpret_cast<float2*>(&C[(size_t)r1 * N + gc]) = make_float2(c0, c1);
                *reinterpret_cast<float2*>(&C[(size_t)r2 * N + gc]) = make_float2(c2, c3);
            } else if (OUTM == 1) {
                *reinterpret_cast<__half2*>(&Ch[(size_t)r1 * N + gc]) = __floats2half2_rn(c0, c1);
                *reinterpret_cast<__half2*>(&Ch[(size_t)r2 * N + gc]) = __floats2half2_rn(c2, c3);
            } else {
                int type = gc >> 9;
                int head = (gc >> 6) & 7;
                int d    = gc & 63;
                int s1 = r1 & (SEQ - 1);
                int s2 = r2 & (SEQ - 1);
                int bi1 = r1 >> 12;
                int bi2 = r2 >> 12;
                size_t oo1 = ((((size_t)bi1 * 8 + head) * SEQ) + s1) * 64 + d;
                size_t oo2 = ((((size_t)bi2 * 8 + head) * SEQ) + s2) * 64 + d;
                if (type == 2) {
                    *reinterpret_cast<__half2*>(&Vp[oo1]) = __floats2half2_rn(c0, c1);
                    *reinterpret_cast<__half2*>(&Vp[oo2]) = __floats2half2_rn(c2, c3);
                } else {
                    float2 cs1 = tab[s1 * 32 + (d >> 1)];
                    float2 cs2 = tab[s2 * 32 + (d >> 1)];
                    float x1 = c0 * cs1.x - c1 * cs1.y;
                    float y1 = c0 * cs1.y + c1 * cs1.x;
                    float x2 = c2 * cs2.x - c3 * cs2.y;
                    float y2 = c2 * cs2.y + c3 * cs2.x;
                    if (type == 0) {
                        *reinterpret_cast<__half2*>(&Qp[oo1]) =
                            __floats2half2_rn(x1 * 0.125f, y1 * 0.125f);
                        *reinterpret_cast<__half2*>(&Qp[oo2]) =
                            __floats2half2_rn(x2 * 0.125f, y2 * 0.125f);
                    } else {
                        *reinterpret_cast<__half2*>(&Kp[oo1]) = __floats2half2_rn(x1, y1);
                        *reinterpret_cast<__half2*>(&Kp[oo2]) = __floats2half2_rn(x2, y2);
                    }
                }
            }
        }
    }
}

// register-resident causal flash attention (identical to round-6/7/8 passing version)
__global__ void __launch_bounds__(128) flash_mma(const __half* __restrict__ Qg,
                                                 const __half* __restrict__ Kg,
                                                 const __half* __restrict__ Vg,
                                                 __half* __restrict__ ctx)
{
    __shared__ __half sQ[4096];
    __shared__ __half sK0[4096];
    __shared__ __half sK1[4096];
    __shared__ __half sV0[4096];
    __shared__ __half sV1[4096];

    int qt = (int)gridDim.x - 1 - blockIdx.x;
    int bh = blockIdx.y;
    int bb = bh >> 3;
    int hh = bh & 7;
    const __half* Qb = Qg + ((size_t)bh * SEQ + qt * 64) * 64;
    const __half* Kb = Kg + (size_t)bh * SEQ * 64;
    const __half* Vb = Vg + (size_t)bh * SEQ * 64;

    int tid = threadIdx.x;
    int lane = tid & 31;
    int wq = tid >> 5;
    int lr = lane & 7;
    int lg = lane >> 3;
    unsigned aQ = smem_u32(sQ);
    unsigned aK0 = smem_u32(sK0);
    unsigned aK1 = smem_u32(sK1);
    unsigned aV0 = smem_u32(sV0);
    unsigned aV1 = smem_u32(sV1);

    {
        int r = tid >> 1;
        int cbase = (tid & 1) * 4;
        #pragma unroll
        for (int c = cbase; c < cbase + 4; c++) {
            CP16(aQ  + r * 128 + ((c ^ (r & 7)) << 4), Qb + r * 64 + c * 8);
            CP16(aK0 + r * 128 + ((c ^ (r & 7)) << 4), Kb + r * 64 + c * 8);
            CP16(aV0 + r * 128 + ((c ^ (r & 7)) << 4), Vb + r * 64 + c * 8);
        }
    }
    CPCOMMIT();
    CPWAIT0();
    __syncthreads();

    unsigned qa[4][4];
    #pragma unroll
    for (int kc = 0; kc < 4; kc++) {
        int qrow = wq * 16 + ((lg & 1) << 3) + lr;
        int qch  = kc * 2 + (lg >> 1);
        LDSM4(qa[kc][0], qa[kc][1], qa[kc][2], qa[kc][3],
              aQ + qrow * 128 + ((qch ^ (qrow & 7)) << 4));
    }

    float O[8][4];
    #pragma unroll
    for (int j = 0; j < 8; j++) {
        O[j][0] = 0.0f; O[j][1] = 0.0f; O[j][2] = 0.0f; O[j][3] = 0.0f;
    }
    float m1 = -1e30f;
    float m2 = -1e30f;
    float l1 = 0.0f;
    float l2 = 0.0f;

    int grow1 = qt * 64 + wq * 16 + (lane >> 2);
    int grow2 = grow1 + 8;

    for (int kt = 0; kt <= qt; ++kt) {
        unsigned curK = (kt & 1) ? aK1 : aK0;
        unsigned curV = (kt & 1) ? aV1 : aV0;
        unsigned nxtK = (kt & 1) ? aK0 : aK1;
        unsigned nxtV = (kt & 1) ? aV0 : aV1;
        if (kt < qt) {
            const __half* Kn = Kb + (size_t)(kt + 1) * 4096;
            const __half* Vn = Vb + (size_t)(kt + 1) * 4096;
            int r = tid >> 1;
            int cbase = (tid & 1) * 4;
            #pragma unroll
            for (int c = cbase; c < cbase + 4; c++) {
                CP16(nxtK + r * 128 + ((c ^ (r & 7)) << 4), Kn + r * 64 + c * 8);
                CP16(nxtV + r * 128 + ((c ^ (r & 7)) << 4), Vn + r * 64 + c * 8);
            }
            CPCOMMIT();
        }

        float S[8][4];
        #pragma unroll
        for (int j = 0; j < 8; j++) {
            S[j][0] = 0.0f; S[j][1] = 0.0f; S[j][2] = 0.0f; S[j][3] = 0.0f;
        }
        #pragma unroll
        for (int ng = 0; ng < 4; ng++) {
            #pragma unroll
            for (int kc = 0; kc < 4; kc++) {
                int krow = ng * 16 + ((lg >> 1) << 3) + lr;
                int kch  = kc * 2 + (lg & 1);
                unsigned b0, b1, b2, b3;
                LDSM4(b0, b1, b2, b3, curK + krow * 128 + ((kch ^ (krow & 7)) << 4));
                MMA168(S[ng * 2][0], S[ng * 2][1], S[ng * 2][2], S[ng * 2][3],
                       qa[kc][0], qa[kc][1], qa[kc][2], qa[kc][3], b0, b1);
                MMA168(S[ng * 2 + 1][0], S[ng * 2 + 1][1], S[ng * 2 + 1][2], S[ng * 2 + 1][3],
                       qa[kc][0], qa[kc][1], qa[kc][2], qa[kc][3], b2, b3);
            }
        }

        if (kt == qt) {
            #pragma unroll
            for (int j = 0; j < 8; j++) {
                int col = kt * 64 + j * 8 + (lane & 3) * 2;
                if (col     > grow1) S[j][0] = -1e30f;
                if (col + 1 > grow1) S[j][1] = -1e30f;
                if (col     > grow2) S[j][2] = -1e30f;
                if (col + 1 > grow2) S[j][3] = -1e30f;
            }
        }

        float mx1 = -1e30f;
        float mx2 = -1e30f;
        #pragma unroll
        for (int j = 0; j < 8; j++) {
            mx1 = fmaxf(mx1, fmaxf(S[j][0], S[j][1]));
            mx2 = fmaxf(mx2, fmaxf(S[j][2], S[j][3]));
        }
        mx1 = fmaxf(mx1, __shfl_xor_sync(0xffffffffu, mx1, 1));
        mx1 = fmaxf(mx1, __shfl_xor_sync(0xffffffffu, mx1, 2));
        mx2 = fmaxf(mx2, __shfl_xor_sync(0xffffffffu, mx2, 1));
        mx2 = fmaxf(mx2, __shfl_xor_sync(0xffffffffu, mx2, 2));
        float mn1 = fmaxf(m1, mx1);
        float mn2 = fmaxf(m2, mx2);
        float al1 = __expf(m1 - mn1);
        float al2 = __expf(m2 - mn2);
        float sm1 = 0.0f;
        float sm2 = 0.0f;
        #pragma unroll
        for (int j = 0; j < 8; j++) {
            S[j][0] = __expf(S[j][0] - mn1);
            S[j][1] = __expf(S[j][1] - mn1);
            S[j][2] = __expf(S[j][2] - mn2);
            S[j][3] = __expf(S[j][3] - mn2);
            sm1 += S[j][0] + S[j][1];
            sm2 += S[j][2] + S[j][3];
        }
        sm1 += __shfl_xor_sync(0xffffffffu, sm1, 1);
        sm1 += __shfl_xor_sync(0xffffffffu, sm1, 2);
        sm2 += __shfl_xor_sync(0xffffffffu, sm2, 1);
        sm2 += __shfl_xor_sync(0xffffffffu, sm2, 2);
        l1 = l1 * al1 + sm1;
        l2 = l2 * al2 + sm2;
        m1 = mn1;
        m2 = mn2;
        #pragma unroll
        for (int j = 0; j < 8; j++) {
            O[j][0] *= al1; O[j][1] *= al1;
            O[j][2] *= al2; O[j][3] *= al2;
        }

        unsigned pa[4][4];
        #pragma unroll
        for (int kc = 0; kc < 4; kc++) {
            pa[kc][0] = pack_h2(S[2 * kc][0],     S[2 * kc][1]);
            pa[kc][1] = pack_h2(S[2 * kc][2],     S[2 * kc][3]);
            pa[kc][2] = pack_h2(S[2 * kc + 1][0], S[2 * kc + 1][1]);
            pa[kc][3] = pack_h2(S[2 * kc + 1][2], S[2 * kc + 1][3]);
        }

        #pragma unroll
        for (int dg = 0; dg < 4; dg++) {
            #pragma unroll
            for (int tc = 0; tc < 4; tc++) {
                int vrow = tc * 16 + ((lg & 1) << 3) + lr;
                int vch  = dg * 2 + (lg >> 1);
                unsigned v0, v1, v2, v3;
                LDSM4T(v0, v1, v2, v3, curV + vrow * 128 + ((vch ^ (vrow & 7)) << 4));
                MMA168(O[dg * 2][0], O[dg * 2][1], O[dg * 2][2], O[dg * 2][3],
                       pa[tc][0], pa[tc][1], pa[tc][2], pa[tc][3], v0, v1);
                MMA168(O[dg * 2 + 1][0], O[dg * 2 + 1][1], O[dg * 2 + 1][2], O[dg * 2 + 1][3],
                       pa[tc][0], pa[tc][1], pa[tc][2], pa[tc][3], v2, v3);
            }
        }

        if (kt < qt) {
            CPWAIT0();
            __syncthreads();
        }
    }

    float inv1 = 1.0f / l1;
    float inv2 = 1.0f / l2;
    size_t base1 = ((size_t)bb * SEQ + grow1) * 512 + hh * 64;
    size_t base2 = ((size_t)bb * SEQ + grow2) * 512 + hh * 64;
    #pragma unroll
    for (int j = 0; j < 8; j++) {
        int col = j * 8 + (lane & 3) * 2;
        *reinterpret_cast<__half2*>(&ctx[base1 + col]) =
            __floats2half2_rn(O[j][0] * inv1, O[j][1] * inv1);
        *reinterpret_cast<__half2*>(&ctx[base2 + col]) =
            __floats2half2_rn(O[j][2] * inv2, O[j][3] * inv2);
    }
}

extern "C" void kernel_launch(void* const* d_in, const int* in_sizes, int n_in,
                              void* d_out, int out_size)
{
    const float* src      = (const float*)d_in[0];
    const float* ln_w     = (const float*)d_in[1];
    const float* ln_b     = (const float*)d_in[2];
    const float* wqkv_w   = (const float*)d_in[3];
    const float* wqkv_b   = (const float*)d_in[4];
    const float* out_w    = (const float*)d_in[5];
    const float* out_b    = (const float*)d_in[6];
    const float* ffn_ln_w = (const float*)d_in[7];
    const float* ffn_ln_b = (const float*)d_in[8];
    const float* ff1_w    = (const float*)d_in[9];
    const float* ff1_b    = (const float*)d_in[10];
    const float* ff2_w    = (const float*)d_in[11];
    const float* ff2_b    = (const float*)d_in[12];
    float* out = (float*)d_out;

    __half *xln, *Q, *K, *V, *ctx, *hid, *wqkvh, *outwh, *ff1h, *ff2h;
    float *src2;
    float2* tab;
    cudaGetSymbolAddress((void**)&xln,   g_xln_h);
    cudaGetSymbolAddress((void**)&Q,     g_Qh);
    cudaGetSymbolAddress((void**)&K,     g_Kh);
    cudaGetSymbolAddress((void**)&V,     g_Vh);
    cudaGetSymbolAddress((void**)&ctx,   g_ctx_h);
    cudaGetSymbolAddress((void**)&src2,  g_src2);
    cudaGetSymbolAddress((void**)&hid,   g_hid_h);
    cudaGetSymbolAddress((void**)&tab,   g_rope);
    cudaGetSymbolAddress((void**)&wqkvh, g_wqkv_h);
    cudaGetSymbolAddress((void**)&outwh, g_outw_h);
    cudaGetSymbolAddress((void**)&ff1h,  g_ff1_h);
    cudaGetSymbolAddress((void**)&ff2h,  g_ff2_h);

    cudaFuncSetAttribute(gemm_mma<false, false, 2>,
                         cudaFuncAttributeMaxDynamicSharedMemorySize, GEMM_SMEM);
    cudaFuncSetAttribute(gemm_mma<false, true, 0>,
                         cudaFuncAttributeMaxDynamicSharedMemorySize, GEMM_SMEM);
    cudaFuncSetAttribute(gemm_mma<true, false, 1>,
                         cudaFuncAttributeMaxDynamicSharedMemorySize, GEMM_SMEM);

    int n4_total = N4_QKV + N4_OUT + N4_FF1 + N4_FF2;
    f2h_all<<<(n4_total + 255) / 256, 256>>>(wqkv_w, out_w, ff1_w, ff2_w,
                                             wqkvh, outwh, ff1h, ff2h);
    rope_tab_kernel<<<(SEQ * 32) / 256, 256>>>(tab);
    ln_kernel<<<ROWS, 128>>>(src, ln_w, ln_b, xln);

    // QKV projection with fused rope + split
    gemm_mma<false, false, 2><<<dim3(12, 64), 256, GEMM_SMEM>>>(
        xln, wqkvh, wqkv_b, nullptr, nullptr, nullptr, Q, K, V, tab,
        ROWS, 3 * D_MODEL, D_MODEL);

    flash_mma<<<dim3(SEQ / 64, BH), 128>>>(Q, K, V, ctx);

    gemm_mma<false, true, 0><<<dim3(4, 64), 256, GEMM_SMEM>>>(
        ctx, outwh, out_b, src, src2, nullptr, nullptr, nullptr, nullptr, nullptr,
        ROWS, D_MODEL, D_MODEL);

    ln_kernel<<<ROWS, 128>>>(src2, ffn_ln_w, ffn_ln_b, xln);

    gemm_mma<true, false, 1><<<dim3(16, 64), 256, GEMM_SMEM>>>(
        xln, ff1h, ff1_b, nullptr, nullptr, hid, nullptr, nullptr, nullptr, nullptr,
        ROWS, D_FF, D_MODEL);

    gemm_mma<false, true, 0><<<dim3(4, 64), 256, GEMM_SMEM>>>(
        hid, ff2h, ff2_b, src2, out, nullptr, nullptr, nullptr, nullptr, nullptr,
        ROWS, D_MODEL, D_FF);
}